// round 2
// baseline (speedup 1.0000x reference)
#include <cuda_runtime.h>
#include <math.h>

#define S_LEN 2048
#define HID   2048
#define NH    32
#define NKV   8
#define HD    64
#define KVDIM (NKV*HD)   /* 512 */

// ---- scratch (allocation-free: device globals) ----
__device__ float g_q[S_LEN*HID];
__device__ float g_k[S_LEN*KVDIM];
__device__ float g_v[S_LEN*KVDIM];
__device__ float g_attn[S_LEN*HID];
__device__ float g_cos[S_LEN*(HD/2)];
__device__ float g_sin[S_LEN*(HD/2)];

// ---------------- RoPE table (double precision for exact range reduction) ----
__global__ void rope_table_kernel() {
    int idx = blockIdx.x*blockDim.x + threadIdx.x;
    if (idx >= S_LEN*(HD/2)) return;
    int i = idx & 31;
    int s = idx >> 5;
    double inv = pow(10000.0, -(double)i / 32.0);
    double ang = (double)s * inv;
    g_cos[idx] = (float)cos(ang);
    g_sin[idx] = (float)sin(ang);
}

// ---------------- apply RoPE to q (32 heads) and k (8 heads) ----
__global__ void rope_apply_kernel() {
    int idx = blockIdx.x*blockDim.x + threadIdx.x;
    const int total = S_LEN*(NH+NKV)*32;
    if (idx >= total) return;
    int i    = idx & 31;
    int head = (idx >> 5) % (NH+NKV);
    int s    = idx / (32*(NH+NKV));
    float c  = g_cos[s*32+i];
    float sn = g_sin[s*32+i];
    float* base;
    if (head < NH) base = g_q + (size_t)s*HID   + head*HD;
    else           base = g_k + (size_t)s*KVDIM + (head-NH)*HD;
    float x1 = base[i], x2 = base[i+32];
    base[i]    = x1*c - x2*sn;
    base[i+32] = x2*c + x1*sn;
}

// ---------------- SGEMM  C[M,N] = A[M,K] * B[N,K]^T  (both K-contiguous) ----
__global__ __launch_bounds__(256) void sgemm_nt(const float* __restrict__ A,
                                                const float* __restrict__ B,
                                                float* __restrict__ C,
                                                int M, int N, int K)
{
    const int BM=128, BN=128, BK=8;
    __shared__ float As[BK][BM];
    __shared__ float Bs[BK][BN];
    int bm = blockIdx.y*BM, bn = blockIdx.x*BN;
    int tid = threadIdx.x;
    int tx = tid & 15, ty = tid >> 4;
    int lrow = tid >> 1;
    int lcol = (tid & 1) * 4;
    float acc[8][8];
    #pragma unroll
    for (int i=0;i<8;i++)
        #pragma unroll
        for (int j=0;j<8;j++) acc[i][j]=0.f;

    for (int k0=0;k0<K;k0+=BK) {
        float4 a4 = *(const float4*)(A + (size_t)(bm+lrow)*K + k0 + lcol);
        float4 b4 = *(const float4*)(B + (size_t)(bn+lrow)*K + k0 + lcol);
        __syncthreads();
        As[lcol+0][lrow]=a4.x; As[lcol+1][lrow]=a4.y;
        As[lcol+2][lrow]=a4.z; As[lcol+3][lrow]=a4.w;
        Bs[lcol+0][lrow]=b4.x; Bs[lcol+1][lrow]=b4.y;
        Bs[lcol+2][lrow]=b4.z; Bs[lcol+3][lrow]=b4.w;
        __syncthreads();
        #pragma unroll
        for (int k=0;k<BK;k++) {
            float ra[8], rb[8];
            #pragma unroll
            for (int i=0;i<8;i++) ra[i]=As[k][ty*8+i];
            #pragma unroll
            for (int j=0;j<8;j++) rb[j]=Bs[k][tx*8+j];
            #pragma unroll
            for (int i=0;i<8;i++)
                #pragma unroll
                for (int j=0;j<8;j++)
                    acc[i][j] += ra[i]*rb[j];
        }
    }
    #pragma unroll
    for (int i=0;i<8;i++) {
        float* cp = C + (size_t)(bm+ty*8+i)*N + bn + tx*8;
        *(float4*)cp     = make_float4(acc[i][0],acc[i][1],acc[i][2],acc[i][3]);
        *(float4*)(cp+4) = make_float4(acc[i][4],acc[i][5],acc[i][6],acc[i][7]);
    }
}

// ---------------- flash attention: 1 thread = 1 query row ----
#define BM_ATT 128
#define BN_ATT 16

__global__ __launch_bounds__(BM_ATT) void flash_attn_kernel()
{
    __shared__ float ks[BN_ATT][HD];
    __shared__ float vs[BN_ATT][HD];
    int row  = blockIdx.x*BM_ATT + threadIdx.x;
    int head = blockIdx.y;
    int kv   = head >> 2;       // GQA: 4 q heads per kv head
    const float scale = 0.125f; // 1/sqrt(64)

    float q[HD];
    const float* qp = g_q + (size_t)row*HID + head*HD;
    #pragma unroll
    for (int d=0;d<HD;d++) q[d] = qp[d]*scale;

    float o[HD];
    #pragma unroll
    for (int d=0;d<HD;d++) o[d]=0.f;
    float m = -1e30f, l = 0.f;

    int kend = blockIdx.x*BM_ATT + BM_ATT;  // causal upper bound for this block
    for (int j0=0; j0<kend; j0+=BN_ATT) {
        __syncthreads();
        {
            int t = threadIdx.x;
            #pragma unroll
            for (int r=0;r<2;r++) {
                int p  = t*2 + r;        // 0..255 float4 slots
                int jr = p >> 4;         // 0..15
                int cc = (p & 15) * 4;   // 0..60
                *(float4*)&ks[jr][cc] = *(const float4*)(g_k + (size_t)(j0+jr)*KVDIM + kv*HD + cc);
                *(float4*)&vs[jr][cc] = *(const float4*)(g_v + (size_t)(j0+jr)*KVDIM + kv*HD + cc);
            }
        }
        __syncthreads();

        float sc[BN_ATT];
        #pragma unroll
        for (int j=0;j<BN_ATT;j++) {
            const float4* kr = (const float4*)ks[j];
            float s0=0.f,s1=0.f,s2=0.f,s3=0.f;
            #pragma unroll
            for (int d4=0; d4<HD/4; d4++) {
                float4 kk = kr[d4];
                s0 += q[d4*4+0]*kk.x;
                s1 += q[d4*4+1]*kk.y;
                s2 += q[d4*4+2]*kk.z;
                s3 += q[d4*4+3]*kk.w;
            }
            float s = (s0+s1)+(s2+s3);
            sc[j] = (j0+j <= row) ? s : -1e30f;
        }
        float mt = sc[0];
        #pragma unroll
        for (int j=1;j<BN_ATT;j++) mt = fmaxf(mt, sc[j]);
        float mnew = fmaxf(m, mt);
        float corr = __expf(m - mnew);
        float psum = 0.f;
        #pragma unroll
        for (int j=0;j<BN_ATT;j++) { sc[j] = __expf(sc[j]-mnew); psum += sc[j]; }
        l = l*corr + psum;
        #pragma unroll
        for (int d=0; d<HD; d++) o[d] *= corr;
        #pragma unroll
        for (int j=0;j<BN_ATT;j++) {
            const float4* vr = (const float4*)vs[j];
            float pj = sc[j];
            #pragma unroll
            for (int d4=0; d4<HD/4; d4++) {
                float4 vv = vr[d4];
                o[d4*4+0] += pj*vv.x;
                o[d4*4+1] += pj*vv.y;
                o[d4*4+2] += pj*vv.z;
                o[d4*4+3] += pj*vv.w;
            }
        }
        m = mnew;
    }
    float invl = 1.f/l;
    float* op = g_attn + (size_t)row*HID + head*HD;
    #pragma unroll
    for (int d=0;d<HD;d++) op[d] = o[d]*invl;
}

extern "C" void kernel_launch(void* const* d_in, const int* in_sizes, int n_in,
                              void* d_out, int out_size)
{
    const float* X  = (const float*)d_in[0];
    const float* Wq = (const float*)d_in[1];
    const float* Wk = (const float*)d_in[2];
    const float* Wv = (const float*)d_in[3];
    const float* Wo = (const float*)d_in[4];
    float* out = (float*)d_out;

    float *q, *k, *v, *attn;
    cudaGetSymbolAddress((void**)&q,    g_q);
    cudaGetSymbolAddress((void**)&k,    g_k);
    cudaGetSymbolAddress((void**)&v,    g_v);
    cudaGetSymbolAddress((void**)&attn, g_attn);

    // QKV projections
    sgemm_nt<<<dim3(HID/128,   S_LEN/128), 256>>>(X, Wq, q, S_LEN, HID,   HID);
    sgemm_nt<<<dim3(KVDIM/128, S_LEN/128), 256>>>(X, Wk, k, S_LEN, KVDIM, HID);
    sgemm_nt<<<dim3(KVDIM/128, S_LEN/128), 256>>>(X, Wv, v, S_LEN, KVDIM, HID);

    // RoPE
    rope_table_kernel<<<(S_LEN*32 + 255)/256, 256>>>();
    rope_apply_kernel<<<(S_LEN*(NH+NKV)*32 + 255)/256, 256>>>();

    // causal GQA flash attention
    flash_attn_kernel<<<dim3(S_LEN/BM_ATT, NH), BM_ATT>>>();

    // output projection
    sgemm_nt<<<dim3(HID/128, S_LEN/128), 256>>>(attn, Wo, out, S_LEN, HID, HID);
}

// round 5
// speedup vs baseline: 1.6101x; 1.6101x over previous
#include <cuda_runtime.h>
#include <math.h>
#include <cstdint>

#define S_LEN 2048
#define HID   2048
#define NH    32
#define NKV   8
#define HD    64
#define KVDIM (NKV*HD)   /* 512 */

// ---- scratch (allocation-free: device globals) ----
__device__ float g_q[S_LEN*HID];
__device__ float g_k[S_LEN*KVDIM];
__device__ float g_v[S_LEN*KVDIM];
__device__ float g_attn[S_LEN*HID];
__device__ float g_cos[S_LEN*(HD/2)];
__device__ float g_sin[S_LEN*(HD/2)];

__device__ __forceinline__ uint32_t f2tf32(float f) {
    uint32_t r; asm("cvt.rna.tf32.f32 %0, %1;" : "=r"(r) : "f"(f)); return r;
}

// =================== tf32 mma.sync GEMM: C[M,N] = A[M,K] * B[N,K]^T ========
// Block tile 128x128x32, 8 warps (2m x 4n), warp tile 64x32, atoms m16n8k8.
// SMEM row-major [m][k], k-stride padded to 36 words -> conflict-free frag LDS.
#define BM 128
#define BN 128
#define BK 32
#define SKW 36   /* BK + 4 pad, in 32-bit words */

__global__ __launch_bounds__(256) void mma_gemm_nt(const float* __restrict__ A,
                                                   const float* __restrict__ B,
                                                   float* __restrict__ C,
                                                   int M, int N, int K)
{
    extern __shared__ uint32_t sm[];              // As[2][BM][SKW], Bs[2][BN][SKW]
    uint32_t* As = sm;
    uint32_t* Bs = sm + 2*BM*SKW;

    const int tid  = threadIdx.x;
    const int warp = tid >> 5, lane = tid & 31;
    const int g    = lane >> 2, tig = lane & 3;
    const int wm   = (warp & 1) * 64;
    const int wn   = (warp >> 1) * 32;
    const int bm   = blockIdx.y * BM, bn = blockIdx.x * BN;

    const int r  = tid >> 1;          // 0..127 (row loaded by this thread)
    const int c8 = (tid & 1) * 4;     // 0 or 4 (first float of the pair-half)

    float acc[4][4][4];
    #pragma unroll
    for (int i=0;i<4;i++)
        #pragma unroll
        for (int j=0;j<4;j++)
            #pragma unroll
            for (int t=0;t<4;t++) acc[i][j][t] = 0.f;

    // Each thread loads 4 float4 per tile per matrix: rows r, k-offsets {c8*4? ...}
    // mapping: pass p in 0..3 covers k quarter p*8 + c8 .. +3
    const float* Ap = A + (size_t)(bm + r) * K;
    const float* Bp = B + (size_t)(bn + r) * K;

    float4 stage_a[4], stage_b[4];

    // prologue loads (k0 = 0)
    #pragma unroll
    for (int p=0;p<4;p++) {
        stage_a[p] = *(const float4*)(Ap + p*8 + c8);
        stage_b[p] = *(const float4*)(Bp + p*8 + c8);
    }
    #pragma unroll
    for (int p=0;p<4;p++) {
        int kk = p*8 + c8;
        uint32_t* as = As + r*SKW + kk;
        uint32_t* bs = Bs + r*SKW + kk;
        as[0]=f2tf32(stage_a[p].x); as[1]=f2tf32(stage_a[p].y);
        as[2]=f2tf32(stage_a[p].z); as[3]=f2tf32(stage_a[p].w);
        bs[0]=f2tf32(stage_b[p].x); bs[1]=f2tf32(stage_b[p].y);
        bs[2]=f2tf32(stage_b[p].z); bs[3]=f2tf32(stage_b[p].w);
    }
    __syncthreads();

    const int NKT = K / BK;
    for (int kt = 0; kt < NKT; ++kt) {
        const int buf = kt & 1;
        const uint32_t* Ab = As + buf*BM*SKW;
        const uint32_t* Bb = Bs + buf*BN*SKW;

        if (kt + 1 < NKT) {                       // issue next global loads early
            int k0 = (kt + 1) * BK;
            #pragma unroll
            for (int p=0;p<4;p++) {
                stage_a[p] = *(const float4*)(Ap + k0 + p*8 + c8);
                stage_b[p] = *(const float4*)(Bp + k0 + p*8 + c8);
            }
        }

        #pragma unroll
        for (int ks = 0; ks < 4; ++ks) {          // 4 x k8 steps
            const int kc = ks * 8;
            uint32_t a[4][4], b[4][2];
            #pragma unroll
            for (int i=0;i<4;i++) {
                const uint32_t* ar = Ab + (wm + 16*i + g)*SKW + kc + tig;
                a[i][0] = ar[0];
                a[i][1] = ar[8*SKW];
                a[i][2] = ar[4];
                a[i][3] = ar[8*SKW + 4];
            }
            #pragma unroll
            for (int j=0;j<4;j++) {
                const uint32_t* br = Bb + (wn + 8*j + g)*SKW + kc + tig;
                b[j][0] = br[0];
                b[j][1] = br[4];
            }
            #pragma unroll
            for (int i=0;i<4;i++)
                #pragma unroll
                for (int j=0;j<4;j++)
                    asm volatile(
                        "mma.sync.aligned.m16n8k8.row.col.f32.tf32.tf32.f32 "
                        "{%0,%1,%2,%3}, {%4,%5,%6,%7}, {%8,%9}, {%0,%1,%2,%3};"
                        : "+f"(acc[i][j][0]), "+f"(acc[i][j][1]),
                          "+f"(acc[i][j][2]), "+f"(acc[i][j][3])
                        : "r"(a[i][0]), "r"(a[i][1]), "r"(a[i][2]), "r"(a[i][3]),
                          "r"(b[j][0]), "r"(b[j][1]));
        }

        if (kt + 1 < NKT) {                       // stage -> other buffer
            uint32_t* As2 = As + (buf^1)*BM*SKW;
            uint32_t* Bs2 = Bs + (buf^1)*BN*SKW;
            #pragma unroll
            for (int p=0;p<4;p++) {
                int kk = p*8 + c8;
                uint32_t* as = As2 + r*SKW + kk;
                uint32_t* bs = Bs2 + r*SKW + kk;
                as[0]=f2tf32(stage_a[p].x); as[1]=f2tf32(stage_a[p].y);
                as[2]=f2tf32(stage_a[p].z); as[3]=f2tf32(stage_a[p].w);
                bs[0]=f2tf32(stage_b[p].x); bs[1]=f2tf32(stage_b[p].y);
                bs[2]=f2tf32(stage_b[p].z); bs[3]=f2tf32(stage_b[p].w);
            }
        }
        __syncthreads();
    }

    // epilogue: write C
    #pragma unroll
    for (int i=0;i<4;i++) {
        #pragma unroll
        for (int j=0;j<4;j++) {
            int row = bm + wm + 16*i + g;
            int col = bn + wn + 8*j + 2*tig;
            *(float2*)(C + (size_t)row*N + col)     = make_float2(acc[i][j][0], acc[i][j][1]);
            *(float2*)(C + (size_t)(row+8)*N + col) = make_float2(acc[i][j][2], acc[i][j][3]);
        }
    }
}

// ---------------- RoPE table (double precision for exact range reduction) ----
__global__ void rope_table_kernel() {
    int idx = blockIdx.x*blockDim.x + threadIdx.x;
    if (idx >= S_LEN*(HD/2)) return;
    int i = idx & 31;
    int s = idx >> 5;
    double inv = pow(10000.0, -(double)i / 32.0);
    double ang = (double)s * inv;
    g_cos[idx] = (float)cos(ang);
    g_sin[idx] = (float)sin(ang);
}

// ---------------- apply RoPE to q (32 heads) and k (8 heads) ----
__global__ void rope_apply_kernel() {
    int idx = blockIdx.x*blockDim.x + threadIdx.x;
    const int total = S_LEN*(NH+NKV)*32;
    if (idx >= total) return;
    int i    = idx & 31;
    int head = (idx >> 5) % (NH+NKV);
    int s    = idx / (32*(NH+NKV));
    float c  = g_cos[s*32+i];
    float sn = g_sin[s*32+i];
    float* base;
    if (head < NH) base = g_q + (size_t)s*HID   + head*HD;
    else           base = g_k + (size_t)s*KVDIM + (head-NH)*HD;
    float x1 = base[i], x2 = base[i+32];
    base[i]    = x1*c - x2*sn;
    base[i+32] = x2*c + x1*sn;
}

// ---------------- flash attention: 1 thread = 1 query row ----
#define BM_ATT 128
#define BN_ATT 16

__global__ __launch_bounds__(BM_ATT) void flash_attn_kernel()
{
    __shared__ float ks[BN_ATT][HD];
    __shared__ float vs[BN_ATT][HD];
    int row  = blockIdx.x*BM_ATT + threadIdx.x;
    int head = blockIdx.y;
    int kv   = head >> 2;       // GQA: 4 q heads per kv head
    const float scale = 0.125f; // 1/sqrt(64)

    float q[HD];
    const float* qp = g_q + (size_t)row*HID + head*HD;
    #pragma unroll
    for (int d=0;d<HD;d++) q[d] = qp[d]*scale;

    float o[HD];
    #pragma unroll
    for (int d=0;d<HD;d++) o[d]=0.f;
    float m = -1e30f, l = 0.f;

    int kend = blockIdx.x*BM_ATT + BM_ATT;  // causal upper bound for this block
    for (int j0=0; j0<kend; j0+=BN_ATT) {
        __syncthreads();
        {
            int t = threadIdx.x;
            #pragma unroll
            for (int rr=0;rr<2;rr++) {
                int p  = t*2 + rr;       // 0..255 float4 slots
                int jr = p >> 4;         // 0..15
                int cc = (p & 15) * 4;   // 0..60
                *(float4*)&ks[jr][cc] = *(const float4*)(g_k + (size_t)(j0+jr)*KVDIM + kv*HD + cc);
                *(float4*)&vs[jr][cc] = *(const float4*)(g_v + (size_t)(j0+jr)*KVDIM + kv*HD + cc);
            }
        }
        __syncthreads();

        float sc[BN_ATT];
        #pragma unroll
        for (int j=0;j<BN_ATT;j++) {
            const float4* kr = (const float4*)ks[j];
            float s0=0.f,s1=0.f,s2=0.f,s3=0.f;
            #pragma unroll
            for (int d4=0; d4<HD/4; d4++) {
                float4 kk = kr[d4];
                s0 += q[d4*4+0]*kk.x;
                s1 += q[d4*4+1]*kk.y;
                s2 += q[d4*4+2]*kk.z;
                s3 += q[d4*4+3]*kk.w;
            }
            float s = (s0+s1)+(s2+s3);
            sc[j] = (j0+j <= row) ? s : -1e30f;
        }
        float mt = sc[0];
        #pragma unroll
        for (int j=1;j<BN_ATT;j++) mt = fmaxf(mt, sc[j]);
        float mnew = fmaxf(m, mt);
        float corr = __expf(m - mnew);
        float psum = 0.f;
        #pragma unroll
        for (int j=0;j<BN_ATT;j++) { sc[j] = __expf(sc[j]-mnew); psum += sc[j]; }
        l = l*corr + psum;
        #pragma unroll
        for (int d=0; d<HD; d++) o[d] *= corr;
        #pragma unroll
        for (int j=0;j<BN_ATT;j++) {
            const float4* vr = (const float4*)vs[j];
            float pj = sc[j];
            #pragma unroll
            for (int d4=0; d4<HD/4; d4++) {
                float4 vv = vr[d4];
                o[d4*4+0] += pj*vv.x;
                o[d4*4+1] += pj*vv.y;
                o[d4*4+2] += pj*vv.z;
                o[d4*4+3] += pj*vv.w;
            }
        }
        m = mnew;
    }
    float invl = 1.f/l;
    float* op = g_attn + (size_t)row*HID + head*HD;
    #pragma unroll
    for (int d=0;d<HD;d++) op[d] = o[d]*invl;
}

extern "C" void kernel_launch(void* const* d_in, const int* in_sizes, int n_in,
                              void* d_out, int out_size)
{
    const float* X  = (const float*)d_in[0];
    const float* Wq = (const float*)d_in[1];
    const float* Wk = (const float*)d_in[2];
    const float* Wv = (const float*)d_in[3];
    const float* Wo = (const float*)d_in[4];
    float* out = (float*)d_out;

    float *q, *k, *v, *attn;
    cudaGetSymbolAddress((void**)&q,    g_q);
    cudaGetSymbolAddress((void**)&k,    g_k);
    cudaGetSymbolAddress((void**)&v,    g_v);
    cudaGetSymbolAddress((void**)&attn, g_attn);

    const int SMEM_DYN = 4 * BM * SKW * 4;  // 73728 B: double-buffered A+B tiles
    cudaFuncSetAttribute(mma_gemm_nt, cudaFuncAttributeMaxDynamicSharedMemorySize, SMEM_DYN);

    // QKV projections (tf32 tensor cores)
    mma_gemm_nt<<<dim3(HID/BN,   S_LEN/BM), 256, SMEM_DYN>>>(X, Wq, q, S_LEN, HID,   HID);
    mma_gemm_nt<<<dim3(KVDIM/BN, S_LEN/BM), 256, SMEM_DYN>>>(X, Wk, k, S_LEN, KVDIM, HID);
    mma_gemm_nt<<<dim3(KVDIM/BN, S_LEN/BM), 256, SMEM_DYN>>>(X, Wv, v, S_LEN, KVDIM, HID);

    // RoPE
    rope_table_kernel<<<(S_LEN*32 + 255)/256, 256>>>();
    rope_apply_kernel<<<(S_LEN*(NH+NKV)*32 + 255)/256, 256>>>();

    // causal GQA flash attention
    flash_attn_kernel<<<dim3(S_LEN/BM_ATT, NH), BM_ATT>>>();

    // output projection (tf32 tensor cores)
    mma_gemm_nt<<<dim3(HID/BN, S_LEN/BM), 256, SMEM_DYN>>>(attn, Wo, out, S_LEN, HID, HID);
}

// round 8
// speedup vs baseline: 2.7012x; 1.6777x over previous
#include <cuda_runtime.h>
#include <math.h>
#include <cstdint>

#define S_LEN 2048
#define HID   2048
#define NH    32
#define NKV   8
#define HD    64
#define KVDIM (NKV*HD)   /* 512 */

// ---- scratch (allocation-free: device globals) ----
__device__ float g_q[S_LEN*HID];
__device__ float g_k[S_LEN*KVDIM];
__device__ float g_v[S_LEN*KVDIM];
__device__ float g_attn[S_LEN*HID];
__device__ float g_cos[S_LEN*(HD/2)];
__device__ float g_sin[S_LEN*(HD/2)];

__device__ __forceinline__ uint32_t f2tf32(float f) {
    uint32_t r; asm("cvt.rna.tf32.f32 %0, %1;" : "=r"(r) : "f"(f)); return r;
}

__device__ __forceinline__ void mma_tf32(float* c, const uint32_t* a, uint32_t b0, uint32_t b1) {
    asm volatile(
        "mma.sync.aligned.m16n8k8.row.col.f32.tf32.tf32.f32 "
        "{%0,%1,%2,%3}, {%4,%5,%6,%7}, {%8,%9}, {%0,%1,%2,%3};"
        : "+f"(c[0]), "+f"(c[1]), "+f"(c[2]), "+f"(c[3])
        : "r"(a[0]), "r"(a[1]), "r"(a[2]), "r"(a[3]), "r"(b0), "r"(b1));
}

// =================== tf32 mma.sync GEMM: C[M,N] = A[M,K] * B[N,K]^T ========
#define BM 128
#define BN 128
#define BK 32
#define SKW 36   /* BK + 4 pad, in 32-bit words */

__global__ __launch_bounds__(256) void mma_gemm_nt(const float* __restrict__ A,
                                                   const float* __restrict__ B,
                                                   float* __restrict__ C,
                                                   int M, int N, int K)
{
    extern __shared__ uint32_t sm[];              // As[2][BM][SKW], Bs[2][BN][SKW]
    uint32_t* As = sm;
    uint32_t* Bs = sm + 2*BM*SKW;

    const int tid  = threadIdx.x;
    const int warp = tid >> 5, lane = tid & 31;
    const int g    = lane >> 2, tig = lane & 3;
    const int wm   = (warp & 1) * 64;
    const int wn   = (warp >> 1) * 32;
    const int bm   = blockIdx.y * BM, bn = blockIdx.x * BN;

    const int r  = tid >> 1;
    const int c8 = (tid & 1) * 4;

    float acc[4][4][4];
    #pragma unroll
    for (int i=0;i<4;i++)
        #pragma unroll
        for (int j=0;j<4;j++)
            #pragma unroll
            for (int t=0;t<4;t++) acc[i][j][t] = 0.f;

    const float* Ap = A + (size_t)(bm + r) * K;
    const float* Bp = B + (size_t)(bn + r) * K;

    float4 stage_a[4], stage_b[4];

    #pragma unroll
    for (int p=0;p<4;p++) {
        stage_a[p] = *(const float4*)(Ap + p*8 + c8);
        stage_b[p] = *(const float4*)(Bp + p*8 + c8);
    }
    #pragma unroll
    for (int p=0;p<4;p++) {
        int kk = p*8 + c8;
        uint32_t* as = As + r*SKW + kk;
        uint32_t* bs = Bs + r*SKW + kk;
        as[0]=f2tf32(stage_a[p].x); as[1]=f2tf32(stage_a[p].y);
        as[2]=f2tf32(stage_a[p].z); as[3]=f2tf32(stage_a[p].w);
        bs[0]=f2tf32(stage_b[p].x); bs[1]=f2tf32(stage_b[p].y);
        bs[2]=f2tf32(stage_b[p].z); bs[3]=f2tf32(stage_b[p].w);
    }
    __syncthreads();

    const int NKT = K / BK;
    for (int kt = 0; kt < NKT; ++kt) {
        const int buf = kt & 1;
        const uint32_t* Ab = As + buf*BM*SKW;
        const uint32_t* Bb = Bs + buf*BN*SKW;

        if (kt + 1 < NKT) {
            int k0 = (kt + 1) * BK;
            #pragma unroll
            for (int p=0;p<4;p++) {
                stage_a[p] = *(const float4*)(Ap + k0 + p*8 + c8);
                stage_b[p] = *(const float4*)(Bp + k0 + p*8 + c8);
            }
        }

        #pragma unroll
        for (int ks = 0; ks < 4; ++ks) {
            const int kc = ks * 8;
            uint32_t a[4][4], b[4][2];
            #pragma unroll
            for (int i=0;i<4;i++) {
                const uint32_t* ar = Ab + (wm + 16*i + g)*SKW + kc + tig;
                a[i][0] = ar[0];
                a[i][1] = ar[8*SKW];
                a[i][2] = ar[4];
                a[i][3] = ar[8*SKW + 4];
            }
            #pragma unroll
            for (int j=0;j<4;j++) {
                const uint32_t* br = Bb + (wn + 8*j + g)*SKW + kc + tig;
                b[j][0] = br[0];
                b[j][1] = br[4];
            }
            #pragma unroll
            for (int i=0;i<4;i++)
                #pragma unroll
                for (int j=0;j<4;j++)
                    mma_tf32(acc[i][j], a[i], b[j][0], b[j][1]);
        }

        if (kt + 1 < NKT) {
            uint32_t* As2 = As + (buf^1)*BM*SKW;
            uint32_t* Bs2 = Bs + (buf^1)*BN*SKW;
            #pragma unroll
            for (int p=0;p<4;p++) {
                int kk = p*8 + c8;
                uint32_t* as = As2 + r*SKW + kk;
                uint32_t* bs = Bs2 + r*SKW + kk;
                as[0]=f2tf32(stage_a[p].x); as[1]=f2tf32(stage_a[p].y);
                as[2]=f2tf32(stage_a[p].z); as[3]=f2tf32(stage_a[p].w);
                bs[0]=f2tf32(stage_b[p].x); bs[1]=f2tf32(stage_b[p].y);
                bs[2]=f2tf32(stage_b[p].z); bs[3]=f2tf32(stage_b[p].w);
            }
        }
        __syncthreads();
    }

    #pragma unroll
    for (int i=0;i<4;i++) {
        #pragma unroll
        for (int j=0;j<4;j++) {
            int row = bm + wm + 16*i + g;
            int col = bn + wn + 8*j + 2*tig;
            *(float2*)(C + (size_t)row*N + col)     = make_float2(acc[i][j][0], acc[i][j][1]);
            *(float2*)(C + (size_t)(row+8)*N + col) = make_float2(acc[i][j][2], acc[i][j][3]);
        }
    }
}

// ---------------- RoPE table (double precision for exact range reduction) ----
__global__ void rope_table_kernel() {
    int idx = blockIdx.x*blockDim.x + threadIdx.x;
    if (idx >= S_LEN*(HD/2)) return;
    int i = idx & 31;
    int s = idx >> 5;
    double inv = pow(10000.0, -(double)i / 32.0);
    double ang = (double)s * inv;
    g_cos[idx] = (float)cos(ang);
    g_sin[idx] = (float)sin(ang);
}

// ---------------- apply RoPE to q (32 heads) and k (8 heads) ----
__global__ void rope_apply_kernel() {
    int idx = blockIdx.x*blockDim.x + threadIdx.x;
    const int total = S_LEN*(NH+NKV)*32;
    if (idx >= total) return;
    int i    = idx & 31;
    int head = (idx >> 5) % (NH+NKV);
    int s    = idx / (32*(NH+NKV));
    float c  = g_cos[s*32+i];
    float sn = g_sin[s*32+i];
    float* base;
    if (head < NH) base = g_q + (size_t)s*HID   + head*HD;
    else           base = g_k + (size_t)s*KVDIM + (head-NH)*HD;
    float x1 = base[i], x2 = base[i+32];
    base[i]    = x1*c - x2*sn;
    base[i+32] = x2*c + x1*sn;
}

// ============ tensor-core flash attention (tf32 mma, causal GQA) ===========
// Block: 128 q-rows x 1 head, 8 warps, warp owns 16 rows. Key tile KT=64.
// K staged [kt][d] (native B layout), V staged transposed [d][kt].
// P round-trips through warp-private SMEM (tf32 words).
#define KT   64
#define PADW 68   /* 64 + 4 pad words */

__global__ __launch_bounds__(256) void flash_attn_tc()
{
    extern __shared__ uint32_t smf[];
    uint32_t* Ks = smf;                   // [64][68]
    uint32_t* Vs = smf + KT*PADW;         // [64][68]  (Vs[d][kt])
    uint32_t* Ps = smf + 2*KT*PADW;       // [8][16][68]

    const int tid  = threadIdx.x;
    const int warp = tid >> 5, lane = tid & 31;
    const int g    = lane >> 2, tig = lane & 3;
    const int qb   = blockIdx.x, h = blockIdx.y;
    const int kvh  = h >> 2;
    const int qr0  = qb*128 + warp*16;

    // Q fragments (scaled by 1/sqrt(64), tf32)
    uint32_t qf[8][4];
    {
        const float* q0 = g_q + (size_t)(qr0 + g)*HID + h*HD;
        const float* q8 = q0 + 8*HID;
        #pragma unroll
        for (int ks=0; ks<8; ks++) {
            qf[ks][0] = f2tf32(0.125f*q0[8*ks + tig]);
            qf[ks][1] = f2tf32(0.125f*q8[8*ks + tig]);
            qf[ks][2] = f2tf32(0.125f*q0[8*ks + tig + 4]);
            qf[ks][3] = f2tf32(0.125f*q8[8*ks + tig + 4]);
        }
    }

    float o[8][4];
    #pragma unroll
    for (int j=0;j<8;j++)
        #pragma unroll
        for (int t=0;t<4;t++) o[j][t] = 0.f;
    float m0 = -1e30f, m1 = -1e30f, l0 = 0.f, l1 = 0.f;

    uint32_t* Pw = Ps + warp*16*PADW;
    const int kend = (qb + 1) * 128;

    for (int kt0 = 0; kt0 < kend; kt0 += KT) {
        __syncthreads();
        // ---- stage K: Ks[kt][d] ----
        {
            int kt  = tid >> 2;
            int seg = (tid & 3) * 16;
            const float* kp = g_k + (size_t)(kt0 + kt)*KVDIM + kvh*HD + seg;
            uint32_t* dst = Ks + kt*PADW + seg;
            #pragma unroll
            for (int u=0; u<4; u++) {
                float4 f = *(const float4*)(kp + 4*u);
                *(uint4*)(dst + 4*u) = make_uint4(f2tf32(f.x), f2tf32(f.y),
                                                  f2tf32(f.z), f2tf32(f.w));
            }
        }
        // ---- stage V transposed: Vs[d][kt] ----
        {
            int kt = tid & 63;
            #pragma unroll
            for (int p=0; p<4; p++) {
                int d0 = (tid >> 6)*4 + p*16;
                float4 f = *(const float4*)(g_v + (size_t)(kt0 + kt)*KVDIM + kvh*HD + d0);
                Vs[(d0+0)*PADW + kt] = f2tf32(f.x);
                Vs[(d0+1)*PADW + kt] = f2tf32(f.y);
                Vs[(d0+2)*PADW + kt] = f2tf32(f.z);
                Vs[(d0+3)*PADW + kt] = f2tf32(f.w);
            }
        }
        __syncthreads();

        if (kt0 <= qr0 + 15) {          // tile not fully masked for this warp
            // ---- S = Q K^T ----
            float s[8][4];
            #pragma unroll
            for (int j=0;j<8;j++)
                #pragma unroll
                for (int t=0;t<4;t++) s[j][t] = 0.f;
            #pragma unroll
            for (int ks=0; ks<8; ks++) {
                #pragma unroll
                for (int jn=0; jn<8; jn++) {
                    const uint32_t* br = Ks + (8*jn + g)*PADW + 8*ks + tig;
                    mma_tf32(s[jn], qf[ks], br[0], br[4]);
                }
            }
            // ---- causal mask (diagonal tiles only) ----
            if (kt0 + KT - 1 > qr0) {
                int r0 = qr0 + g, r1 = r0 + 8;
                #pragma unroll
                for (int jn=0; jn<8; jn++) {
                    int col = kt0 + 8*jn + 2*tig;
                    if (col     > r0) s[jn][0] = -1e30f;
                    if (col + 1 > r0) s[jn][1] = -1e30f;
                    if (col     > r1) s[jn][2] = -1e30f;
                    if (col + 1 > r1) s[jn][3] = -1e30f;
                }
            }
            // ---- online softmax ----
            float t0 = -1e30f, t1 = -1e30f;
            #pragma unroll
            for (int jn=0; jn<8; jn++) {
                t0 = fmaxf(t0, fmaxf(s[jn][0], s[jn][1]));
                t1 = fmaxf(t1, fmaxf(s[jn][2], s[jn][3]));
            }
            t0 = fmaxf(t0, __shfl_xor_sync(0xffffffffu, t0, 1));
            t0 = fmaxf(t0, __shfl_xor_sync(0xffffffffu, t0, 2));
            t1 = fmaxf(t1, __shfl_xor_sync(0xffffffffu, t1, 1));
            t1 = fmaxf(t1, __shfl_xor_sync(0xffffffffu, t1, 2));
            float mn0 = fmaxf(m0, t0), mn1 = fmaxf(m1, t1);
            float c0 = __expf(m0 - mn0), c1 = __expf(m1 - mn1);
            float ps0 = 0.f, ps1 = 0.f;
            #pragma unroll
            for (int jn=0; jn<8; jn++) {
                s[jn][0] = __expf(s[jn][0] - mn0);
                s[jn][1] = __expf(s[jn][1] - mn0);
                s[jn][2] = __expf(s[jn][2] - mn1);
                s[jn][3] = __expf(s[jn][3] - mn1);
                ps0 += s[jn][0] + s[jn][1];
                ps1 += s[jn][2] + s[jn][3];
            }
            l0 = l0*c0 + ps0;  l1 = l1*c1 + ps1;
            m0 = mn0;  m1 = mn1;
            #pragma unroll
            for (int jn=0; jn<8; jn++) {
                o[jn][0] *= c0; o[jn][1] *= c0;
                o[jn][2] *= c1; o[jn][3] *= c1;
            }
            // ---- store P (warp-private, tf32) ----
            #pragma unroll
            for (int jn=0; jn<8; jn++) {
                *(uint2*)(Pw + g*PADW     + 8*jn + 2*tig) = make_uint2(f2tf32(s[jn][0]), f2tf32(s[jn][1]));
                *(uint2*)(Pw + (g+8)*PADW + 8*jn + 2*tig) = make_uint2(f2tf32(s[jn][2]), f2tf32(s[jn][3]));
            }
            __syncwarp();
            // ---- O += P V ----
            #pragma unroll
            for (int ks=0; ks<8; ks++) {
                uint32_t a[4];
                const uint32_t* pr0 = Pw + g*PADW     + 8*ks + tig;
                const uint32_t* pr8 = Pw + (g+8)*PADW + 8*ks + tig;
                a[0] = pr0[0]; a[1] = pr8[0]; a[2] = pr0[4]; a[3] = pr8[4];
                #pragma unroll
                for (int jn=0; jn<8; jn++) {
                    const uint32_t* vr = Vs + (8*jn + g)*PADW + 8*ks + tig;
                    mma_tf32(o[jn], a, vr[0], vr[4]);
                }
            }
        }
    }

    // ---- finalize: cross-tig l sums, normalize, write ----
    l0 += __shfl_xor_sync(0xffffffffu, l0, 1);
    l0 += __shfl_xor_sync(0xffffffffu, l0, 2);
    l1 += __shfl_xor_sync(0xffffffffu, l1, 1);
    l1 += __shfl_xor_sync(0xffffffffu, l1, 2);
    float inv0 = 1.f/l0, inv1 = 1.f/l1;
    float* o0 = g_attn + (size_t)(qr0 + g)*HID + h*HD;
    float* o8 = o0 + 8*HID;
    #pragma unroll
    for (int jn=0; jn<8; jn++) {
        *(float2*)(o0 + 8*jn + 2*tig) = make_float2(o[jn][0]*inv0, o[jn][1]*inv0);
        *(float2*)(o8 + 8*jn + 2*tig) = make_float2(o[jn][2]*inv1, o[jn][3]*inv1);
    }
}

extern "C" void kernel_launch(void* const* d_in, const int* in_sizes, int n_in,
                              void* d_out, int out_size)
{
    const float* X  = (const float*)d_in[0];
    const float* Wq = (const float*)d_in[1];
    const float* Wk = (const float*)d_in[2];
    const float* Wv = (const float*)d_in[3];
    const float* Wo = (const float*)d_in[4];
    float* out = (float*)d_out;

    float *q, *k, *v, *attn;
    cudaGetSymbolAddress((void**)&q,    g_q);
    cudaGetSymbolAddress((void**)&k,    g_k);
    cudaGetSymbolAddress((void**)&v,    g_v);
    cudaGetSymbolAddress((void**)&attn, g_attn);

    const int SMEM_DYN = 4 * BM * SKW * 4;  // 73728 B
    cudaFuncSetAttribute(mma_gemm_nt, cudaFuncAttributeMaxDynamicSharedMemorySize, SMEM_DYN);
    const int SMEM_ATT = (2*KT*PADW + 8*16*PADW) * 4;  // 69632 B
    cudaFuncSetAttribute(flash_attn_tc, cudaFuncAttributeMaxDynamicSharedMemorySize, SMEM_ATT);

    // QKV projections (tf32 tensor cores)
    mma_gemm_nt<<<dim3(HID/BN,   S_LEN/BM), 256, SMEM_DYN>>>(X, Wq, q, S_LEN, HID,   HID);
    mma_gemm_nt<<<dim3(KVDIM/BN, S_LEN/BM), 256, SMEM_DYN>>>(X, Wk, k, S_LEN, KVDIM, HID);
    mma_gemm_nt<<<dim3(KVDIM/BN, S_LEN/BM), 256, SMEM_DYN>>>(X, Wv, v, S_LEN, KVDIM, HID);

    // RoPE
    rope_table_kernel<<<(S_LEN*32 + 255)/256, 256>>>();
    rope_apply_kernel<<<(S_LEN*(NH+NKV)*32 + 255)/256, 256>>>();

    // causal GQA flash attention (tensor cores)
    flash_attn_tc<<<dim3(S_LEN/128, NH), 256, SMEM_ATT>>>();

    // output projection (tf32 tensor cores)
    mma_gemm_nt<<<dim3(HID/BN, S_LEN/BM), 256, SMEM_DYN>>>(attn, Wo, out, S_LEN, HID, HID);
}

// round 10
// speedup vs baseline: 3.4295x; 1.2696x over previous
#include <cuda_runtime.h>
#include <math.h>
#include <cstdint>

#define S_LEN 2048
#define HID   2048
#define NH    32
#define NKV   8
#define HD    64
#define KVDIM (NKV*HD)   /* 512 */

// ---- scratch (allocation-free: device globals) ----
__device__ float g_q[S_LEN*HID];
__device__ float g_k[S_LEN*KVDIM];
__device__ float g_v[S_LEN*KVDIM];
__device__ float g_attn[S_LEN*HID];
__device__ float g_cos[S_LEN*(HD/2)];
__device__ float g_sin[S_LEN*(HD/2)];

__device__ __forceinline__ uint32_t f2tf32(float f) {
    uint32_t r; asm("cvt.rna.tf32.f32 %0, %1;" : "=r"(r) : "f"(f)); return r;
}

__device__ __forceinline__ void mma_tf32(float* c, const uint32_t* a, uint32_t b0, uint32_t b1) {
    asm volatile(
        "mma.sync.aligned.m16n8k8.row.col.f32.tf32.tf32.f32 "
        "{%0,%1,%2,%3}, {%4,%5,%6,%7}, {%8,%9}, {%0,%1,%2,%3};"
        : "+f"(c[0]), "+f"(c[1]), "+f"(c[2]), "+f"(c[3])
        : "r"(a[0]), "r"(a[1]), "r"(a[2]), "r"(a[3]), "r"(b0), "r"(b1));
}

// =================== tf32 mma.sync GEMM core: C[*,N] = A[*,2048] B[N,2048]^T
#define BM 128
#define BN 128
#define BK 32
#define SKW 36   /* BK + 4 pad, in 32-bit words */

__device__ __forceinline__ void gemm_core(const float* __restrict__ A,
                                          const float* __restrict__ B,
                                          float* __restrict__ C,
                                          int N, int bm, int bn,
                                          uint32_t* sm)
{
    const int K = HID;
    uint32_t* As = sm;
    uint32_t* Bs = sm + 2*BM*SKW;

    const int tid  = threadIdx.x;
    const int warp = tid >> 5, lane = tid & 31;
    const int g    = lane >> 2, tig = lane & 3;
    const int wm   = (warp & 1) * 64;
    const int wn   = (warp >> 1) * 32;

    const int r  = tid >> 1;
    const int c8 = (tid & 1) * 4;

    float acc[4][4][4];
    #pragma unroll
    for (int i=0;i<4;i++)
        #pragma unroll
        for (int j=0;j<4;j++)
            #pragma unroll
            for (int t=0;t<4;t++) acc[i][j][t] = 0.f;

    const float* Ap = A + (size_t)(bm + r) * K;
    const float* Bp = B + (size_t)(bn + r) * K;

    float4 stage_a[4], stage_b[4];

    #pragma unroll
    for (int p=0;p<4;p++) {
        stage_a[p] = *(const float4*)(Ap + p*8 + c8);
        stage_b[p] = *(const float4*)(Bp + p*8 + c8);
    }
    #pragma unroll
    for (int p=0;p<4;p++) {
        int kk = p*8 + c8;
        uint32_t* as = As + r*SKW + kk;
        uint32_t* bs = Bs + r*SKW + kk;
        as[0]=f2tf32(stage_a[p].x); as[1]=f2tf32(stage_a[p].y);
        as[2]=f2tf32(stage_a[p].z); as[3]=f2tf32(stage_a[p].w);
        bs[0]=f2tf32(stage_b[p].x); bs[1]=f2tf32(stage_b[p].y);
        bs[2]=f2tf32(stage_b[p].z); bs[3]=f2tf32(stage_b[p].w);
    }
    __syncthreads();

    const int NKT = K / BK;
    for (int kt = 0; kt < NKT; ++kt) {
        const int buf = kt & 1;
        const uint32_t* Ab = As + buf*BM*SKW;
        const uint32_t* Bb = Bs + buf*BN*SKW;

        if (kt + 1 < NKT) {
            int k0 = (kt + 1) * BK;
            #pragma unroll
            for (int p=0;p<4;p++) {
                stage_a[p] = *(const float4*)(Ap + k0 + p*8 + c8);
                stage_b[p] = *(const float4*)(Bp + k0 + p*8 + c8);
            }
        }

        #pragma unroll
        for (int ks = 0; ks < 4; ++ks) {
            const int kc = ks * 8;
            uint32_t a[4][4], b[4][2];
            #pragma unroll
            for (int i=0;i<4;i++) {
                const uint32_t* ar = Ab + (wm + 16*i + g)*SKW + kc + tig;
                a[i][0] = ar[0];
                a[i][1] = ar[8*SKW];
                a[i][2] = ar[4];
                a[i][3] = ar[8*SKW + 4];
            }
            #pragma unroll
            for (int j=0;j<4;j++) {
                const uint32_t* br = Bb + (wn + 8*j + g)*SKW + kc + tig;
                b[j][0] = br[0];
                b[j][1] = br[4];
            }
            #pragma unroll
            for (int i=0;i<4;i++)
                #pragma unroll
                for (int j=0;j<4;j++)
                    mma_tf32(acc[i][j], a[i], b[j][0], b[j][1]);
        }

        if (kt + 1 < NKT) {
            uint32_t* As2 = As + (buf^1)*BM*SKW;
            uint32_t* Bs2 = Bs + (buf^1)*BN*SKW;
            #pragma unroll
            for (int p=0;p<4;p++) {
                int kk = p*8 + c8;
                uint32_t* as = As2 + r*SKW + kk;
                uint32_t* bs = Bs2 + r*SKW + kk;
                as[0]=f2tf32(stage_a[p].x); as[1]=f2tf32(stage_a[p].y);
                as[2]=f2tf32(stage_a[p].z); as[3]=f2tf32(stage_a[p].w);
                bs[0]=f2tf32(stage_b[p].x); bs[1]=f2tf32(stage_b[p].y);
                bs[2]=f2tf32(stage_b[p].z); bs[3]=f2tf32(stage_b[p].w);
            }
        }
        __syncthreads();
    }

    #pragma unroll
    for (int i=0;i<4;i++) {
        #pragma unroll
        for (int j=0;j<4;j++) {
            int row = bm + wm + 16*i + g;
            int col = bn + wn + 8*j + 2*tig;
            *(float2*)(C + (size_t)row*N + col)     = make_float2(acc[i][j][0], acc[i][j][1]);
            *(float2*)(C + (size_t)(row+8)*N + col) = make_float2(acc[i][j][2], acc[i][j][3]);
        }
    }
}

// Fused Q/K/V projection: grid (24, 16). bx<16 -> Q, 16..19 -> K, 20..23 -> V.
__global__ __launch_bounds__(256, 2) void qkv_gemm(const float* __restrict__ X,
                                                   const float* __restrict__ Wq,
                                                   const float* __restrict__ Wk,
                                                   const float* __restrict__ Wv)
{
    extern __shared__ uint32_t sm[];
    const int bx = blockIdx.x, bm = blockIdx.y * BM;
    const float* Bsel;  float* Csel;  int N, bn;
    if (bx < 16)      { Bsel = Wq; Csel = g_q; N = HID;   bn = bx*BN; }
    else if (bx < 20) { Bsel = Wk; Csel = g_k; N = KVDIM; bn = (bx-16)*BN; }
    else              { Bsel = Wv; Csel = g_v; N = KVDIM; bn = (bx-20)*BN; }
    gemm_core(X, Bsel, Csel, N, bm, bn, sm);
}

// Output projection: out = attn * Wo^T
__global__ __launch_bounds__(256, 2) void wo_gemm(const float* __restrict__ Wo,
                                                  float* __restrict__ out)
{
    extern __shared__ uint32_t sm[];
    gemm_core(g_attn, Wo, out, HID, blockIdx.y*BM, blockIdx.x*BN, sm);
}

// ---------------- RoPE table: double range-reduction + float sincos ----------
__global__ void rope_table_kernel() {
    int idx = blockIdx.x*blockDim.x + threadIdx.x;
    if (idx >= S_LEN*(HD/2)) return;
    int i = idx & 31;
    int s = idx >> 5;
    // inv_freq = 10000^(-i/32) = 2^(-i*log2(10000)/32)
    double inv = exp2(-(double)i * (13.287712379549449 / 32.0));
    double ang = (double)s * inv;
    const double TWO_PI = 6.283185307179586476925;
    ang -= TWO_PI * floor(ang / TWO_PI);
    float c, sn;
    sincosf((float)ang, &sn, &c);
    g_cos[idx] = c;
    g_sin[idx] = sn;
}

// ============ tensor-core flash attention, fused RoPE (tf32, causal GQA) ====
// Block: 128 q-rows x 1 head, 8 warps, warp owns 16 rows. Key tile KT=64.
// RoPE applied to Q at frag build (registers) and K at SMEM staging.
#define KT   64
#define PADW 68   /* 64 + 4 pad words */

__global__ __launch_bounds__(256) void flash_attn_tc()
{
    extern __shared__ uint32_t smf[];
    uint32_t* Ks = smf;                   // [64][68]
    uint32_t* Vs = smf + KT*PADW;         // [64][68]  (Vs[d][kt])
    uint32_t* Ps = smf + 2*KT*PADW;       // [8][16][68]

    const int tid  = threadIdx.x;
    const int warp = tid >> 5, lane = tid & 31;
    const int g    = lane >> 2, tig = lane & 3;
    const int qb   = blockIdx.x, h = blockIdx.y;
    const int kvh  = h >> 2;
    const int qr0  = qb*128 + warp*16;

    // ---- Q fragments with fused RoPE (scaled by 1/sqrt(64), tf32) ----
    uint32_t qf[8][4];
    {
        const float* q0 = g_q + (size_t)(qr0 + g)*HID + h*HD;
        const float* q8 = q0 + 8*HID;
        const float* cr0 = g_cos + (size_t)(qr0 + g)*32;
        const float* sr0 = g_sin + (size_t)(qr0 + g)*32;
        const float* cr8 = cr0 + 8*32;
        const float* sr8 = sr0 + 8*32;
        float x0[8], x0p[8], x8[8], x8p[8];
        #pragma unroll
        for (int ks=0; ks<8; ks++) {
            x0[ks]  = q0[8*ks + tig];
            x0p[ks] = q0[8*ks + tig + 4];
            x8[ks]  = q8[8*ks + tig];
            x8p[ks] = q8[8*ks + tig + 4];
        }
        #pragma unroll
        for (int ks=0; ks<4; ks++) {
            int i1 = 8*ks + tig, i2 = i1 + 4;
            float c0a=cr0[i1], s0a=sr0[i1], c0b=cr0[i2], s0b=sr0[i2];
            float c8a=cr8[i1], s8a=sr8[i1], c8b=cr8[i2], s8b=sr8[i2];
            qf[ks  ][0] = f2tf32(0.125f*(x0[ks]  *c0a - x0[ks+4] *s0a));
            qf[ks+4][0] = f2tf32(0.125f*(x0[ks+4]*c0a + x0[ks]   *s0a));
            qf[ks  ][2] = f2tf32(0.125f*(x0p[ks] *c0b - x0p[ks+4]*s0b));
            qf[ks+4][2] = f2tf32(0.125f*(x0p[ks+4]*c0b + x0p[ks] *s0b));
            qf[ks  ][1] = f2tf32(0.125f*(x8[ks]  *c8a - x8[ks+4] *s8a));
            qf[ks+4][1] = f2tf32(0.125f*(x8[ks+4]*c8a + x8[ks]   *s8a));
            qf[ks  ][3] = f2tf32(0.125f*(x8p[ks] *c8b - x8p[ks+4]*s8b));
            qf[ks+4][3] = f2tf32(0.125f*(x8p[ks+4]*c8b + x8p[ks] *s8b));
        }
    }

    float o[8][4];
    #pragma unroll
    for (int j=0;j<8;j++)
        #pragma unroll
        for (int t=0;t<4;t++) o[j][t] = 0.f;
    float m0 = -1e30f, m1 = -1e30f, l0 = 0.f, l1 = 0.f;

    uint32_t* Pw = Ps + warp*16*PADW;
    const int kend = (qb + 1) * 128;

    for (int kt0 = 0; kt0 < kend; kt0 += KT) {
        __syncthreads();
        // ---- stage K with fused RoPE: Ks[kt][d] ----
        {
            int kt = tid >> 2, j = tid & 3;   // 4 threads/row; j covers d pair-sets
            int row = kt0 + kt;
            const float* kp = g_k + (size_t)row*KVDIM + kvh*HD;
            int d1 = 8*j;                     // first-half base (0..24)
            float4 xa  = *(const float4*)(kp + d1);
            float4 xa2 = *(const float4*)(kp + d1 + 4);
            float4 xb  = *(const float4*)(kp + d1 + 32);
            float4 xb2 = *(const float4*)(kp + d1 + 36);
            const float* cp = g_cos + (size_t)row*32 + d1;
            const float* sp = g_sin + (size_t)row*32 + d1;
            float4 c  = *(const float4*)cp;
            float4 c2 = *(const float4*)(cp + 4);
            float4 s  = *(const float4*)sp;
            float4 s2 = *(const float4*)(sp + 4);
            uint32_t* dst = Ks + kt*PADW + d1;
            *(uint4*)(dst)      = make_uint4(f2tf32(xa.x*c.x  - xb.x*s.x),
                                             f2tf32(xa.y*c.y  - xb.y*s.y),
                                             f2tf32(xa.z*c.z  - xb.z*s.z),
                                             f2tf32(xa.w*c.w  - xb.w*s.w));
            *(uint4*)(dst + 4)  = make_uint4(f2tf32(xa2.x*c2.x - xb2.x*s2.x),
                                             f2tf32(xa2.y*c2.y - xb2.y*s2.y),
                                             f2tf32(xa2.z*c2.z - xb2.z*s2.z),
                                             f2tf32(xa2.w*c2.w - xb2.w*s2.w));
            *(uint4*)(dst + 32) = make_uint4(f2tf32(xb.x*c.x  + xa.x*s.x),
                                             f2tf32(xb.y*c.y  + xa.y*s.y),
                                             f2tf32(xb.z*c.z  + xa.z*s.z),
                                             f2tf32(xb.w*c.w  + xa.w*s.w));
            *(uint4*)(dst + 36) = make_uint4(f2tf32(xb2.x*c2.x + xa2.x*s2.x),
                                             f2tf32(xb2.y*c2.y + xa2.y*s2.y),
                                             f2tf32(xb2.z*c2.z + xa2.z*s2.z),
                                             f2tf32(xb2.w*c2.w + xa2.w*s2.w));
        }
        // ---- stage V transposed: Vs[d][kt] ----
        {
            int kt = tid & 63;
            #pragma unroll
            for (int p=0; p<4; p++) {
                int d0 = (tid >> 6)*4 + p*16;
                float4 f = *(const float4*)(g_v + (size_t)(kt0 + kt)*KVDIM + kvh*HD + d0);
                Vs[(d0+0)*PADW + kt] = f2tf32(f.x);
                Vs[(d0+1)*PADW + kt] = f2tf32(f.y);
                Vs[(d0+2)*PADW + kt] = f2tf32(f.z);
                Vs[(d0+3)*PADW + kt] = f2tf32(f.w);
            }
        }
        __syncthreads();

        if (kt0 <= qr0 + 15) {          // tile not fully masked for this warp
            // ---- S = Q K^T ----
            float s[8][4];
            #pragma unroll
            for (int j=0;j<8;j++)
                #pragma unroll
                for (int t=0;t<4;t++) s[j][t] = 0.f;
            #pragma unroll
            for (int ks=0; ks<8; ks++) {
                #pragma unroll
                for (int jn=0; jn<8; jn++) {
                    const uint32_t* br = Ks + (8*jn + g)*PADW + 8*ks + tig;
                    mma_tf32(s[jn], qf[ks], br[0], br[4]);
                }
            }
            // ---- causal mask (diagonal tiles only) ----
            if (kt0 + KT - 1 > qr0) {
                int r0 = qr0 + g, r1 = r0 + 8;
                #pragma unroll
                for (int jn=0; jn<8; jn++) {
                    int col = kt0 + 8*jn + 2*tig;
                    if (col     > r0) s[jn][0] = -1e30f;
                    if (col + 1 > r0) s[jn][1] = -1e30f;
                    if (col     > r1) s[jn][2] = -1e30f;
                    if (col + 1 > r1) s[jn][3] = -1e30f;
                }
            }
            // ---- online softmax ----
            float t0 = -1e30f, t1 = -1e30f;
            #pragma unroll
            for (int jn=0; jn<8; jn++) {
                t0 = fmaxf(t0, fmaxf(s[jn][0], s[jn][1]));
                t1 = fmaxf(t1, fmaxf(s[jn][2], s[jn][3]));
            }
            t0 = fmaxf(t0, __shfl_xor_sync(0xffffffffu, t0, 1));
            t0 = fmaxf(t0, __shfl_xor_sync(0xffffffffu, t0, 2));
            t1 = fmaxf(t1, __shfl_xor_sync(0xffffffffu, t1, 1));
            t1 = fmaxf(t1, __shfl_xor_sync(0xffffffffu, t1, 2));
            float mn0 = fmaxf(m0, t0), mn1 = fmaxf(m1, t1);
            float c0 = __expf(m0 - mn0), c1 = __expf(m1 - mn1);
            float ps0 = 0.f, ps1 = 0.f;
            #pragma unroll
            for (int jn=0; jn<8; jn++) {
                s[jn][0] = __expf(s[jn][0] - mn0);
                s[jn][1] = __expf(s[jn][1] - mn0);
                s[jn][2] = __expf(s[jn][2] - mn1);
                s[jn][3] = __expf(s[jn][3] - mn1);
                ps0 += s[jn][0] + s[jn][1];
                ps1 += s[jn][2] + s[jn][3];
            }
            l0 = l0*c0 + ps0;  l1 = l1*c1 + ps1;
            m0 = mn0;  m1 = mn1;
            #pragma unroll
            for (int jn=0; jn<8; jn++) {
                o[jn][0] *= c0; o[jn][1] *= c0;
                o[jn][2] *= c1; o[jn][3] *= c1;
            }
            // ---- store P (warp-private, tf32) ----
            #pragma unroll
            for (int jn=0; jn<8; jn++) {
                *(uint2*)(Pw + g*PADW     + 8*jn + 2*tig) = make_uint2(f2tf32(s[jn][0]), f2tf32(s[jn][1]));
                *(uint2*)(Pw + (g+8)*PADW + 8*jn + 2*tig) = make_uint2(f2tf32(s[jn][2]), f2tf32(s[jn][3]));
            }
            __syncwarp();
            // ---- O += P V ----
            #pragma unroll
            for (int ks=0; ks<8; ks++) {
                uint32_t a[4];
                const uint32_t* pr0 = Pw + g*PADW     + 8*ks + tig;
                const uint32_t* pr8 = Pw + (g+8)*PADW + 8*ks + tig;
                a[0] = pr0[0]; a[1] = pr8[0]; a[2] = pr0[4]; a[3] = pr8[4];
                #pragma unroll
                for (int jn=0; jn<8; jn++) {
                    const uint32_t* vr = Vs + (8*jn + g)*PADW + 8*ks + tig;
                    mma_tf32(o[jn], a, vr[0], vr[4]);
                }
            }
        }
    }

    // ---- finalize ----
    l0 += __shfl_xor_sync(0xffffffffu, l0, 1);
    l0 += __shfl_xor_sync(0xffffffffu, l0, 2);
    l1 += __shfl_xor_sync(0xffffffffu, l1, 1);
    l1 += __shfl_xor_sync(0xffffffffu, l1, 2);
    float inv0 = 1.f/l0, inv1 = 1.f/l1;
    float* o0 = g_attn + (size_t)(qr0 + g)*HID + h*HD;
    float* o8 = o0 + 8*HID;
    #pragma unroll
    for (int jn=0; jn<8; jn++) {
        *(float2*)(o0 + 8*jn + 2*tig) = make_float2(o[jn][0]*inv0, o[jn][1]*inv0);
        *(float2*)(o8 + 8*jn + 2*tig) = make_float2(o[jn][2]*inv1, o[jn][3]*inv1);
    }
}

extern "C" void kernel_launch(void* const* d_in, const int* in_sizes, int n_in,
                              void* d_out, int out_size)
{
    const float* X  = (const float*)d_in[0];
    const float* Wq = (const float*)d_in[1];
    const float* Wk = (const float*)d_in[2];
    const float* Wv = (const float*)d_in[3];
    const float* Wo = (const float*)d_in[4];
    float* out = (float*)d_out;

    const int SMEM_DYN = 4 * BM * SKW * 4;  // 73728 B
    cudaFuncSetAttribute(qkv_gemm, cudaFuncAttributeMaxDynamicSharedMemorySize, SMEM_DYN);
    cudaFuncSetAttribute(wo_gemm,  cudaFuncAttributeMaxDynamicSharedMemorySize, SMEM_DYN);
    const int SMEM_ATT = (2*KT*PADW + 8*16*PADW) * 4;  // 69632 B
    cudaFuncSetAttribute(flash_attn_tc, cudaFuncAttributeMaxDynamicSharedMemorySize, SMEM_ATT);

    // RoPE table first (cheap; ready before attention)
    rope_table_kernel<<<(S_LEN*32 + 255)/256, 256>>>();

    // fused QKV projection (tf32 tensor cores), single launch
    qkv_gemm<<<dim3(24, S_LEN/BM), 256, SMEM_DYN>>>(X, Wq, Wk, Wv);

    // causal GQA flash attention with fused RoPE (tensor cores)
    flash_attn_tc<<<dim3(S_LEN/128, NH), 256, SMEM_ATT>>>();

    // output projection (tf32 tensor cores)
    wo_gemm<<<dim3(HID/BN, S_LEN/BM), 256, SMEM_DYN>>>(Wo, out);
}

// round 13
// speedup vs baseline: 3.7328x; 1.0884x over previous
#include <cuda_runtime.h>
#include <math.h>
#include <cstdint>

#define S_LEN 2048
#define HID   2048
#define NH    32
#define NKV   8
#define HD    64
#define KVDIM (NKV*HD)   /* 512 */

// ---- scratch (allocation-free: device globals) ----
__device__ float g_q[S_LEN*HID];
__device__ float g_k[S_LEN*KVDIM];
__device__ float g_v[S_LEN*KVDIM];
__device__ float g_attn[S_LEN*HID];
__device__ float g_cos[S_LEN*(HD/2)];
__device__ float g_sin[S_LEN*(HD/2)];

__device__ __forceinline__ uint32_t f2tf32(float f) {
    uint32_t r; asm("cvt.rna.tf32.f32 %0, %1;" : "=r"(r) : "f"(f)); return r;
}
__device__ __forceinline__ uint32_t smem_u32(const void* p) {
    uint32_t a;
    asm("{ .reg .u64 t; cvta.to.shared.u64 t, %1; cvt.u32.u64 %0, t; }" : "=r"(a) : "l"(p));
    return a;
}
__device__ __forceinline__ void cp_async16(uint32_t dst, const void* src) {
    asm volatile("cp.async.cg.shared.global [%0], [%1], 16;"
                 :: "r"(dst), "l"(__cvta_generic_to_global(src)) : "memory");
}
#define CP_COMMIT() asm volatile("cp.async.commit_group;" ::: "memory")
#define CP_WAIT0()  asm volatile("cp.async.wait_group 0;" ::: "memory")

__device__ __forceinline__ void mma_tf32(float* c, const uint32_t* a, uint32_t b0, uint32_t b1) {
    asm volatile(
        "mma.sync.aligned.m16n8k8.row.col.f32.tf32.tf32.f32 "
        "{%0,%1,%2,%3}, {%4,%5,%6,%7}, {%8,%9}, {%0,%1,%2,%3};"
        : "+f"(c[0]), "+f"(c[1]), "+f"(c[2]), "+f"(c[3])
        : "r"(a[0]), "r"(a[1]), "r"(a[2]), "r"(a[3]), "r"(b0), "r"(b1));
}

// =================== tf32 mma.sync GEMM core: C[*,N] = A[*,2048] B[N,2048]^T
// Staging via cp.async (no STS, no staging regs); fp32 in smem, cvt at frag load.
#define BM 128
#define BN 128
#define BK 32
#define SKW 36   /* BK + 4 pad, in 32-bit words */

__device__ __forceinline__ void gemm_core(const float* __restrict__ A,
                                          const float* __restrict__ B,
                                          float* __restrict__ C,
                                          int N, int bm, int bn,
                                          uint32_t sbase)
{
    const int K = HID;
    const uint32_t AsB = sbase;                   // byte base of A buffers
    const uint32_t BsB = sbase + 2*BM*SKW*4;      // byte base of B buffers

    const int tid  = threadIdx.x;
    const int warp = tid >> 5, lane = tid & 31;
    const int g    = lane >> 2, tig = lane & 3;
    const int wm   = (warp & 1) * 64;
    const int wn   = (warp >> 1) * 32;

    const int r  = tid >> 1;          // row this thread stages
    const int c8 = (tid & 1) * 4;     // word offset within 8-word group

    float acc[4][4][4];
    #pragma unroll
    for (int i=0;i<4;i++)
        #pragma unroll
        for (int j=0;j<4;j++)
            #pragma unroll
            for (int t=0;t<4;t++) acc[i][j][t] = 0.f;

    const float* Ap = A + (size_t)(bm + r) * K;
    const float* Bp = B + (size_t)(bn + r) * K;
    const uint32_t rowA = AsB + (r*SKW)*4;
    const uint32_t rowB = BsB + (r*SKW)*4;

    // prologue: stage k-chunk 0 into buffer 0
    #pragma unroll
    for (int p=0;p<4;p++) {
        int kk = p*8 + c8;
        cp_async16(rowA + kk*4, Ap + kk);
        cp_async16(rowB + kk*4, Bp + kk);
    }
    CP_COMMIT();
    CP_WAIT0();
    __syncthreads();

    const int NKT = K / BK;
    for (int kt = 0; kt < NKT; ++kt) {
        const int buf = kt & 1;
        const uint32_t AbB = AsB + buf*BM*SKW*4;
        const uint32_t BbB = BsB + buf*BM*SKW*4;

        if (kt + 1 < NKT) {                  // prefetch next chunk into other buffer
            int k0 = (kt + 1) * BK;
            uint32_t dA = AsB + (buf^1)*BM*SKW*4 + (r*SKW)*4;
            uint32_t dB = BsB + (buf^1)*BM*SKW*4 + (r*SKW)*4;
            #pragma unroll
            for (int p=0;p<4;p++) {
                int kk = p*8 + c8;
                cp_async16(dA + kk*4, Ap + k0 + kk);
                cp_async16(dB + kk*4, Bp + k0 + kk);
            }
            CP_COMMIT();
        }

        const uint32_t* Ab = (const uint32_t*)__cvta_shared_to_generic(AbB);
        const uint32_t* Bb = (const uint32_t*)__cvta_shared_to_generic(BbB);
        #pragma unroll
        for (int ks = 0; ks < 4; ++ks) {
            const int kc = ks * 8;
            uint32_t a[4][4], b[4][2];
            #pragma unroll
            for (int i=0;i<4;i++) {
                const uint32_t* ar = Ab + (wm + 16*i + g)*SKW + kc + tig;
                a[i][0] = f2tf32(__uint_as_float(ar[0]));
                a[i][1] = f2tf32(__uint_as_float(ar[8*SKW]));
                a[i][2] = f2tf32(__uint_as_float(ar[4]));
                a[i][3] = f2tf32(__uint_as_float(ar[8*SKW + 4]));
            }
            #pragma unroll
            for (int j=0;j<4;j++) {
                const uint32_t* br = Bb + (wn + 8*j + g)*SKW + kc + tig;
                b[j][0] = f2tf32(__uint_as_float(br[0]));
                b[j][1] = f2tf32(__uint_as_float(br[4]));
            }
            #pragma unroll
            for (int i=0;i<4;i++)
                #pragma unroll
                for (int j=0;j<4;j++)
                    mma_tf32(acc[i][j], a[i], b[j][0], b[j][1]);
        }

        CP_WAIT0();
        __syncthreads();
    }

    #pragma unroll
    for (int i=0;i<4;i++) {
        #pragma unroll
        for (int j=0;j<4;j++) {
            int row = bm + wm + 16*i + g;
            int col = bn + wn + 8*j + 2*tig;
            *(float2*)(C + (size_t)row*N + col)     = make_float2(acc[i][j][0], acc[i][j][1]);
            *(float2*)(C + (size_t)(row+8)*N + col) = make_float2(acc[i][j][2], acc[i][j][3]);
        }
    }
}

// Fused QKV projection + RoPE table.
// grid (25, 16): bx<16 -> Q, 16..19 -> K, 20..23 -> V, bx==24 -> rope table slice.
__global__ __launch_bounds__(256, 2) void qkv_gemm(const float* __restrict__ X,
                                                   const float* __restrict__ Wq,
                                                   const float* __restrict__ Wk,
                                                   const float* __restrict__ Wv)
{
    extern __shared__ uint32_t sm[];
    const int bx = blockIdx.x, by = blockIdx.y;
    if (bx == 24) {
        // rope table: 65536 entries, 16 blocks x 256 threads x 16 entries
        int base = by*4096 + threadIdx.x*16;
        #pragma unroll
        for (int e = 0; e < 16; e++) {
            int idx = base + e;
            int i = idx & 31;
            int s = idx >> 5;
            double inv = exp2(-(double)i * (13.287712379549449 / 32.0));
            double ang = (double)s * inv;
            const double TWO_PI = 6.283185307179586476925;
            ang -= TWO_PI * floor(ang / TWO_PI);
            float c, sn;
            sincosf((float)ang, &sn, &c);
            g_cos[idx] = c;
            g_sin[idx] = sn;
        }
        return;
    }
    const int bm = by * BM;
    const float* Bsel;  float* Csel;  int N, bn;
    if (bx < 16)      { Bsel = Wq; Csel = g_q; N = HID;   bn = bx*BN; }
    else if (bx < 20) { Bsel = Wk; Csel = g_k; N = KVDIM; bn = (bx-16)*BN; }
    else              { Bsel = Wv; Csel = g_v; N = KVDIM; bn = (bx-20)*BN; }
    gemm_core(X, Bsel, Csel, N, bm, bn, smem_u32(sm));
}

// Output projection: out = attn * Wo^T
__global__ __launch_bounds__(256, 2) void wo_gemm(const float* __restrict__ Wo,
                                                  float* __restrict__ out)
{
    extern __shared__ uint32_t sm[];
    gemm_core(g_attn, Wo, out, HID, blockIdx.y*BM, blockIdx.x*BN, smem_u32(sm));
}

// ============ tensor-core flash attention, fused RoPE (tf32, causal GQA) ====
// Block: 128 q-rows x 1 head, 8 warps, warp owns 16 rows. Key tile KT=64.
// Heavy blocks (high qb) scheduled first via reversed blockIdx.x.
#define KT   64
#define PADW 68   /* 64 + 4 pad words */

__global__ __launch_bounds__(256, 2) void flash_attn_tc()
{
    extern __shared__ uint32_t smf[];
    uint32_t* Ks = smf;                   // [64][68]
    uint32_t* Vs = smf + KT*PADW;         // [64][68]  (Vs[d][kt])
    uint32_t* Ps = smf + 2*KT*PADW;       // [8][16][68]

    const int tid  = threadIdx.x;
    const int warp = tid >> 5, lane = tid & 31;
    const int g    = lane >> 2, tig = lane & 3;
    const int qb   = gridDim.x - 1 - blockIdx.x;   // heavy-first
    const int h    = blockIdx.y;
    const int kvh  = h >> 2;
    const int qr0  = qb*128 + warp*16;

    // ---- Q fragments with fused RoPE (scaled by 1/sqrt(64), tf32) ----
    uint32_t qf[8][4];
    {
        const float* q0 = g_q + (size_t)(qr0 + g)*HID + h*HD;
        const float* q8 = q0 + 8*HID;
        const float* cr0 = g_cos + (size_t)(qr0 + g)*32;
        const float* sr0 = g_sin + (size_t)(qr0 + g)*32;
        const float* cr8 = cr0 + 8*32;
        const float* sr8 = sr0 + 8*32;
        float x0[8], x0p[8], x8[8], x8p[8];
        #pragma unroll
        for (int ks=0; ks<8; ks++) {
            x0[ks]  = q0[8*ks + tig];
            x0p[ks] = q0[8*ks + tig + 4];
            x8[ks]  = q8[8*ks + tig];
            x8p[ks] = q8[8*ks + tig + 4];
        }
        #pragma unroll
        for (int ks=0; ks<4; ks++) {
            int i1 = 8*ks + tig, i2 = i1 + 4;
            float c0a=cr0[i1], s0a=sr0[i1], c0b=cr0[i2], s0b=sr0[i2];
            float c8a=cr8[i1], s8a=sr8[i1], c8b=cr8[i2], s8b=sr8[i2];
            qf[ks  ][0] = f2tf32(0.125f*(x0[ks]  *c0a - x0[ks+4] *s0a));
            qf[ks+4][0] = f2tf32(0.125f*(x0[ks+4]*c0a + x0[ks]   *s0a));
            qf[ks  ][2] = f2tf32(0.125f*(x0p[ks] *c0b - x0p[ks+4]*s0b));
            qf[ks+4][2] = f2tf32(0.125f*(x0p[ks+4]*c0b + x0p[ks] *s0b));
            qf[ks  ][1] = f2tf32(0.125f*(x8[ks]  *c8a - x8[ks+4] *s8a));
            qf[ks+4][1] = f2tf32(0.125f*(x8[ks+4]*c8a + x8[ks]   *s8a));
            qf[ks  ][3] = f2tf32(0.125f*(x8p[ks] *c8b - x8p[ks+4]*s8b));
            qf[ks+4][3] = f2tf32(0.125f*(x8p[ks+4]*c8b + x8p[ks] *s8b));
        }
    }

    float o[8][4];
    #pragma unroll
    for (int j=0;j<8;j++)
        #pragma unroll
        for (int t=0;t<4;t++) o[j][t] = 0.f;
    float m0 = -1e30f, m1 = -1e30f, l0 = 0.f, l1 = 0.f;

    uint32_t* Pw = Ps + warp*16*PADW;
    const int kend = (qb + 1) * 128;

    for (int kt0 = 0; kt0 < kend; kt0 += KT) {
        __syncthreads();
        // ---- stage K with fused RoPE: Ks[kt][d] ----
        {
            int kt = tid >> 2, j = tid & 3;
            int row = kt0 + kt;
            const float* kp = g_k + (size_t)row*KVDIM + kvh*HD;
            int d1 = 8*j;
            float4 xa  = *(const float4*)(kp + d1);
            float4 xa2 = *(const float4*)(kp + d1 + 4);
            float4 xb  = *(const float4*)(kp + d1 + 32);
            float4 xb2 = *(const float4*)(kp + d1 + 36);
            const float* cp = g_cos + (size_t)row*32 + d1;
            const float* sp = g_sin + (size_t)row*32 + d1;
            float4 c  = *(const float4*)cp;
            float4 c2 = *(const float4*)(cp + 4);
            float4 s  = *(const float4*)sp;
            float4 s2 = *(const float4*)(sp + 4);
            uint32_t* dst = Ks + kt*PADW + d1;
            *(uint4*)(dst)      = make_uint4(f2tf32(xa.x*c.x  - xb.x*s.x),
                                             f2tf32(xa.y*c.y  - xb.y*s.y),
                                             f2tf32(xa.z*c.z  - xb.z*s.z),
                                             f2tf32(xa.w*c.w  - xb.w*s.w));
            *(uint4*)(dst + 4)  = make_uint4(f2tf32(xa2.x*c2.x - xb2.x*s2.x),
                                             f2tf32(xa2.y*c2.y - xb2.y*s2.y),
                                             f2tf32(xa2.z*c2.z - xb2.z*s2.z),
                                             f2tf32(xa2.w*c2.w - xb2.w*s2.w));
            *(uint4*)(dst + 32) = make_uint4(f2tf32(xb.x*c.x  + xa.x*s.x),
                                             f2tf32(xb.y*c.y  + xa.y*s.y),
                                             f2tf32(xb.z*c.z  + xa.z*s.z),
                                             f2tf32(xb.w*c.w  + xa.w*s.w));
            *(uint4*)(dst + 36) = make_uint4(f2tf32(xb2.x*c2.x + xa2.x*s2.x),
                                             f2tf32(xb2.y*c2.y + xa2.y*s2.y),
                                             f2tf32(xb2.z*c2.z + xa2.z*s2.z),
                                             f2tf32(xb2.w*c2.w + xa2.w*s2.w));
        }
        // ---- stage V transposed: Vs[d][kt] ----
        {
            int kt = tid & 63;
            #pragma unroll
            for (int p=0; p<4; p++) {
                int d0 = (tid >> 6)*4 + p*16;
                float4 f = *(const float4*)(g_v + (size_t)(kt0 + kt)*KVDIM + kvh*HD + d0);
                Vs[(d0+0)*PADW + kt] = f2tf32(f.x);
                Vs[(d0+1)*PADW + kt] = f2tf32(f.y);
                Vs[(d0+2)*PADW + kt] = f2tf32(f.z);
                Vs[(d0+3)*PADW + kt] = f2tf32(f.w);
            }
        }
        __syncthreads();

        if (kt0 <= qr0 + 15) {          // tile not fully masked for this warp
            // ---- S = Q K^T ----
            float s[8][4];
            #pragma unroll
            for (int j=0;j<8;j++)
                #pragma unroll
                for (int t=0;t<4;t++) s[j][t] = 0.f;
            #pragma unroll
            for (int ks=0; ks<8; ks++) {
                #pragma unroll
                for (int jn=0; jn<8; jn++) {
                    const uint32_t* br = Ks + (8*jn + g)*PADW + 8*ks + tig;
                    mma_tf32(s[jn], qf[ks], br[0], br[4]);
                }
            }
            // ---- causal mask (diagonal tiles only) ----
            if (kt0 + KT - 1 > qr0) {
                int r0 = qr0 + g, r1 = r0 + 8;
                #pragma unroll
                for (int jn=0; jn<8; jn++) {
                    int col = kt0 + 8*jn + 2*tig;
                    if (col     > r0) s[jn][0] = -1e30f;
                    if (col + 1 > r0) s[jn][1] = -1e30f;
                    if (col     > r1) s[jn][2] = -1e30f;
                    if (col + 1 > r1) s[jn][3] = -1e30f;
                }
            }
            // ---- online softmax ----
            float t0 = -1e30f, t1 = -1e30f;
            #pragma unroll
            for (int jn=0; jn<8; jn++) {
                t0 = fmaxf(t0, fmaxf(s[jn][0], s[jn][1]));
                t1 = fmaxf(t1, fmaxf(s[jn][2], s[jn][3]));
            }
            t0 = fmaxf(t0, __shfl_xor_sync(0xffffffffu, t0, 1));
            t0 = fmaxf(t0, __shfl_xor_sync(0xffffffffu, t0, 2));
            t1 = fmaxf(t1, __shfl_xor_sync(0xffffffffu, t1, 1));
            t1 = fmaxf(t1, __shfl_xor_sync(0xffffffffu, t1, 2));
            float mn0 = fmaxf(m0, t0), mn1 = fmaxf(m1, t1);
            float c0 = __expf(m0 - mn0), c1 = __expf(m1 - mn1);
            float ps0 = 0.f, ps1 = 0.f;
            #pragma unroll
            for (int jn=0; jn<8; jn++) {
                s[jn][0] = __expf(s[jn][0] - mn0);
                s[jn][1] = __expf(s[jn][1] - mn0);
                s[jn][2] = __expf(s[jn][2] - mn1);
                s[jn][3] = __expf(s[jn][3] - mn1);
                ps0 += s[jn][0] + s[jn][1];
                ps1 += s[jn][2] + s[jn][3];
            }
            l0 = l0*c0 + ps0;  l1 = l1*c1 + ps1;
            m0 = mn0;  m1 = mn1;
            #pragma unroll
            for (int jn=0; jn<8; jn++) {
                o[jn][0] *= c0; o[jn][1] *= c0;
                o[jn][2] *= c1; o[jn][3] *= c1;
            }
            // ---- store P (warp-private, tf32) ----
            #pragma unroll
            for (int jn=0; jn<8; jn++) {
                *(uint2*)(Pw + g*PADW     + 8*jn + 2*tig) = make_uint2(f2tf32(s[jn][0]), f2tf32(s[jn][1]));
                *(uint2*)(Pw + (g+8)*PADW + 8*jn + 2*tig) = make_uint2(f2tf32(s[jn][2]), f2tf32(s[jn][3]));
            }
            __syncwarp();
            // ---- O += P V ----
            #pragma unroll
            for (int ks=0; ks<8; ks++) {
                uint32_t a[4];
                const uint32_t* pr0 = Pw + g*PADW     + 8*ks + tig;
                const uint32_t* pr8 = Pw + (g+8)*PADW + 8*ks + tig;
                a[0] = pr0[0]; a[1] = pr8[0]; a[2] = pr0[4]; a[3] = pr8[4];
                #pragma unroll
                for (int jn=0; jn<8; jn++) {
                    const uint32_t* vr = Vs + (8*jn + g)*PADW + 8*ks + tig;
                    mma_tf32(o[jn], a, vr[0], vr[4]);
                }
            }
        }
    }

    // ---- finalize ----
    l0 += __shfl_xor_sync(0xffffffffu, l0, 1);
    l0 += __shfl_xor_sync(0xffffffffu, l0, 2);
    l1 += __shfl_xor_sync(0xffffffffu, l1, 1);
    l1 += __shfl_xor_sync(0xffffffffu, l1, 2);
    float inv0 = 1.f/l0, inv1 = 1.f/l1;
    float* o0 = g_attn + (size_t)(qr0 + g)*HID + h*HD;
    float* o8 = o0 + 8*HID;
    #pragma unroll
    for (int jn=0; jn<8; jn++) {
        *(float2*)(o0 + 8*jn + 2*tig) = make_float2(o[jn][0]*inv0, o[jn][1]*inv0);
        *(float2*)(o8 + 8*jn + 2*tig) = make_float2(o[jn][2]*inv1, o[jn][3]*inv1);
    }
}

extern "C" void kernel_launch(void* const* d_in, const int* in_sizes, int n_in,
                              void* d_out, int out_size)
{
    const float* X  = (const float*)d_in[0];
    const float* Wq = (const float*)d_in[1];
    const float* Wk = (const float*)d_in[2];
    const float* Wv = (const float*)d_in[3];
    const float* Wo = (const float*)d_in[4];
    float* out = (float*)d_out;

    const int SMEM_DYN = 4 * BM * SKW * 4;  // 73728 B
    cudaFuncSetAttribute(qkv_gemm, cudaFuncAttributeMaxDynamicSharedMemorySize, SMEM_DYN);
    cudaFuncSetAttribute(wo_gemm,  cudaFuncAttributeMaxDynamicSharedMemorySize, SMEM_DYN);
    const int SMEM_ATT = (2*KT*PADW + 8*16*PADW) * 4;  // 69632 B
    cudaFuncSetAttribute(flash_attn_tc, cudaFuncAttributeMaxDynamicSharedMemorySize, SMEM_ATT);

    // fused QKV projection + rope table (single launch)
    qkv_gemm<<<dim3(25, S_LEN/BM), 256, SMEM_DYN>>>(X, Wq, Wk, Wv);

    // causal GQA flash attention with fused RoPE (tensor cores, heavy-first)
    flash_attn_tc<<<dim3(S_LEN/128, NH), 256, SMEM_ATT>>>();

    // output projection (tf32 tensor cores)
    wo_gemm<<<dim3(HID/BN, S_LEN/BM), 256, SMEM_DYN>>>(Wo, out);
}

// round 16
// speedup vs baseline: 3.7565x; 1.0063x over previous
#include <cuda_runtime.h>
#include <math.h>
#include <cstdint>

#define S_LEN 2048
#define HID   2048
#define NH    32
#define NKV   8
#define HD    64
#define KVDIM (NKV*HD)   /* 512 */

// ---- scratch (allocation-free: device globals) ----
__device__ __align__(16) float g_q[S_LEN*HID];
__device__ __align__(16) float g_k[S_LEN*KVDIM];
__device__ __align__(16) float g_v[S_LEN*KVDIM];
__device__ __align__(16) float g_attn[S_LEN*HID];
__device__ __align__(16) float g_cos[S_LEN*(HD/2)];
__device__ __align__(16) float g_sin[S_LEN*(HD/2)];
// tf32-rounded copies of the inputs
__device__ __align__(16) float g_Xc[S_LEN*HID];
__device__ __align__(16) float g_Wqc[HID*HID];
__device__ __align__(16) float g_Wkc[KVDIM*HID];
__device__ __align__(16) float g_Wvc[KVDIM*HID];
__device__ __align__(16) float g_Woc[HID*HID];

__device__ __forceinline__ uint32_t f2tf32(float f) {
    uint32_t r; asm("cvt.rna.tf32.f32 %0, %1;" : "=r"(r) : "f"(f)); return r;
}
__device__ __forceinline__ float rnd_tf32(float f) { return __uint_as_float(f2tf32(f)); }

__device__ __forceinline__ void cp_async16(uint32_t dst, const void* src) {
    asm volatile("cp.async.cg.shared.global [%0], [%1], 16;"
                 :: "r"(dst), "l"(__cvta_generic_to_global(src)) : "memory");
}
#define CP_COMMIT() asm volatile("cp.async.commit_group;" ::: "memory")
#define CP_WAIT0()  asm volatile("cp.async.wait_group 0;" ::: "memory")

__device__ __forceinline__ uint32_t smem_u32(const void* p) {
    uint32_t a;
    asm("{ .reg .u64 t; cvta.to.shared.u64 t, %1; cvt.u32.u64 %0, t; }" : "=r"(a) : "l"(p));
    return a;
}

__device__ __forceinline__ void mma_tf32(float* c, const uint32_t* a, uint32_t b0, uint32_t b1) {
    asm volatile(
        "mma.sync.aligned.m16n8k8.row.col.f32.tf32.tf32.f32 "
        "{%0,%1,%2,%3}, {%4,%5,%6,%7}, {%8,%9}, {%0,%1,%2,%3};"
        : "+f"(c[0]), "+f"(c[1]), "+f"(c[2]), "+f"(c[3])
        : "r"(a[0]), "r"(a[1]), "r"(a[2]), "r"(a[3]), "r"(b0), "r"(b1));
}

// ------------- tf32 pre-rounding pass over all 5 inputs (float4 grid-stride)
__global__ void cvt_inputs(const float4* __restrict__ X,  const float4* __restrict__ Wq,
                           const float4* __restrict__ Wk, const float4* __restrict__ Wv,
                           const float4* __restrict__ Wo)
{
    const int NX  = S_LEN*HID/4;     // 1048576
    const int NWQ = HID*HID/4;       // 1048576
    const int NWK = KVDIM*HID/4;     // 262144
    const int TOT = NX + NWQ + 2*NWK + NWQ;
    float4* dX  = (float4*)g_Xc;
    float4* dWq = (float4*)g_Wqc;
    float4* dWk = (float4*)g_Wkc;
    float4* dWv = (float4*)g_Wvc;
    float4* dWo = (float4*)g_Woc;
    int stride = gridDim.x*blockDim.x;
    for (int i = blockIdx.x*blockDim.x + threadIdx.x; i < TOT; i += stride) {
        const float4* src; float4* dst; int off;
        if (i < NX)                        { src = X;  dst = dX;  off = i; }
        else if (i < NX+NWQ)               { src = Wq; dst = dWq; off = i - NX; }
        else if (i < NX+NWQ+NWK)           { src = Wk; dst = dWk; off = i - NX - NWQ; }
        else if (i < NX+NWQ+2*NWK)         { src = Wv; dst = dWv; off = i - NX - NWQ - NWK; }
        else                               { src = Wo; dst = dWo; off = i - NX - NWQ - 2*NWK; }
        float4 v = src[off];
        dst[off] = make_float4(rnd_tf32(v.x), rnd_tf32(v.y), rnd_tf32(v.z), rnd_tf32(v.w));
    }
}

// =================== tf32 mma.sync GEMM core: C[*,N] = A[*,2048] B[N,2048]^T
// Inputs pre-rounded to tf32 grid -> fragments feed MMA directly (no cvt).
#define BM 128
#define BN 128
#define BK 32
#define SKW 36   /* BK + 4 pad, in 32-bit words */

template<bool ROUND_OUT>
__device__ __forceinline__ void gemm_core(const float* __restrict__ A,
                                          const float* __restrict__ B,
                                          float* __restrict__ C,
                                          int N, int bm, int bn,
                                          uint32_t sbase)
{
    const int K = HID;
    const uint32_t AsB = sbase;
    const uint32_t BsB = sbase + 2*BM*SKW*4;

    const int tid  = threadIdx.x;
    const int warp = tid >> 5, lane = tid & 31;
    const int g    = lane >> 2, tig = lane & 3;
    const int wm   = (warp & 1) * 64;
    const int wn   = (warp >> 1) * 32;

    const int r  = tid >> 1;
    const int c8 = (tid & 1) * 4;

    float acc[4][4][4];
    #pragma unroll
    for (int i=0;i<4;i++)
        #pragma unroll
        for (int j=0;j<4;j++)
            #pragma unroll
            for (int t=0;t<4;t++) acc[i][j][t] = 0.f;

    const float* Ap = A + (size_t)(bm + r) * K;
    const float* Bp = B + (size_t)(bn + r) * K;
    const uint32_t rowA = AsB + (r*SKW)*4;
    const uint32_t rowB = BsB + (r*SKW)*4;

    #pragma unroll
    for (int p=0;p<4;p++) {
        int kk = p*8 + c8;
        cp_async16(rowA + kk*4, Ap + kk);
        cp_async16(rowB + kk*4, Bp + kk);
    }
    CP_COMMIT();
    CP_WAIT0();
    __syncthreads();

    const int NKT = K / BK;
    for (int kt = 0; kt < NKT; ++kt) {
        const int buf = kt & 1;
        const uint32_t AbB = AsB + buf*BM*SKW*4;
        const uint32_t BbB = BsB + buf*BM*SKW*4;

        if (kt + 1 < NKT) {
            int k0 = (kt + 1) * BK;
            uint32_t dA = AsB + (buf^1)*BM*SKW*4 + (r*SKW)*4;
            uint32_t dB = BsB + (buf^1)*BM*SKW*4 + (r*SKW)*4;
            #pragma unroll
            for (int p=0;p<4;p++) {
                int kk = p*8 + c8;
                cp_async16(dA + kk*4, Ap + k0 + kk);
                cp_async16(dB + kk*4, Bp + k0 + kk);
            }
            CP_COMMIT();
        }

        const uint32_t* Ab = (const uint32_t*)__cvta_shared_to_generic(AbB);
        const uint32_t* Bb = (const uint32_t*)__cvta_shared_to_generic(BbB);
        #pragma unroll
        for (int ks = 0; ks < 4; ++ks) {
            const int kc = ks * 8;
            uint32_t a[4][4], b[4][2];
            #pragma unroll
            for (int i=0;i<4;i++) {
                const uint32_t* ar = Ab + (wm + 16*i + g)*SKW + kc + tig;
                a[i][0] = ar[0];
                a[i][1] = ar[8*SKW];
                a[i][2] = ar[4];
                a[i][3] = ar[8*SKW + 4];
            }
            #pragma unroll
            for (int j=0;j<4;j++) {
                const uint32_t* br = Bb + (wn + 8*j + g)*SKW + kc + tig;
                b[j][0] = br[0];
                b[j][1] = br[4];
            }
            #pragma unroll
            for (int i=0;i<4;i++)
                #pragma unroll
                for (int j=0;j<4;j++)
                    mma_tf32(acc[i][j], a[i], b[j][0], b[j][1]);
        }

        CP_WAIT0();
        __syncthreads();
    }

    #pragma unroll
    for (int i=0;i<4;i++) {
        #pragma unroll
        for (int j=0;j<4;j++) {
            int row = bm + wm + 16*i + g;
            int col = bn + wn + 8*j + 2*tig;
            if (ROUND_OUT) {
                *(float2*)(C + (size_t)row*N + col)     = make_float2(rnd_tf32(acc[i][j][0]), rnd_tf32(acc[i][j][1]));
                *(float2*)(C + (size_t)(row+8)*N + col) = make_float2(rnd_tf32(acc[i][j][2]), rnd_tf32(acc[i][j][3]));
            } else {
                *(float2*)(C + (size_t)row*N + col)     = make_float2(acc[i][j][0], acc[i][j][1]);
                *(float2*)(C + (size_t)(row+8)*N + col) = make_float2(acc[i][j][2], acc[i][j][3]);
            }
        }
    }
}

// Fused QKV projection + RoPE table. grid (25, 16).
__global__ __launch_bounds__(256, 2) void qkv_gemm()
{
    extern __shared__ uint32_t sm[];
    const int bx = blockIdx.x, by = blockIdx.y;
    if (bx == 24) {
        int base = by*4096 + threadIdx.x*16;
        #pragma unroll
        for (int e = 0; e < 16; e++) {
            int idx = base + e;
            int i = idx & 31;
            int s = idx >> 5;
            double inv = exp2(-(double)i * (13.287712379549449 / 32.0));
            double ang = (double)s * inv;
            const double TWO_PI = 6.283185307179586476925;
            ang -= TWO_PI * floor(ang / TWO_PI);
            float c, sn;
            sincosf((float)ang, &sn, &c);
            g_cos[idx] = c;
            g_sin[idx] = sn;
        }
        return;
    }
    const int bm = by * BM;
    const float* Bsel;  float* Csel;  int N, bn;
    if (bx < 16)      { Bsel = g_Wqc; Csel = g_q; N = HID;   bn = bx*BN; }
    else if (bx < 20) { Bsel = g_Wkc; Csel = g_k; N = KVDIM; bn = (bx-16)*BN; }
    else              { Bsel = g_Wvc; Csel = g_v; N = KVDIM; bn = (bx-20)*BN; }
    gemm_core<true>(g_Xc, Bsel, Csel, N, bm, bn, smem_u32(sm));
}

// Output projection: out = attn * Wo^T (final fp32, no rounding)
__global__ __launch_bounds__(256, 2) void wo_gemm(float* __restrict__ out)
{
    extern __shared__ uint32_t sm[];
    gemm_core<false>(g_attn, g_Woc, out, HID, blockIdx.y*BM, blockIdx.x*BN, smem_u32(sm));
}

// ============ tensor-core flash attention, fused RoPE (tf32, causal GQA) ====
#define KT   64
#define PADW 68   /* 64 + 4 pad words */

__global__ __launch_bounds__(256, 2) void flash_attn_tc()
{
    extern __shared__ uint32_t smf[];
    uint32_t* Ks = smf;                   // [64][68]
    uint32_t* Vs = smf + KT*PADW;         // [64][68]  (Vs[d][kt])
    uint32_t* Ps = smf + 2*KT*PADW;       // [8][16][68]

    const int tid  = threadIdx.x;
    const int warp = tid >> 5, lane = tid & 31;
    const int g    = lane >> 2, tig = lane & 3;
    const int qb   = gridDim.x - 1 - blockIdx.x;   // heavy-first
    const int h    = blockIdx.y;
    const int kvh  = h >> 2;
    const int qr0  = qb*128 + warp*16;

    // ---- Q fragments with fused RoPE (scaled by 1/sqrt(64), tf32) ----
    uint32_t qf[8][4];
    {
        const float* q0 = g_q + (size_t)(qr0 + g)*HID + h*HD;
        const float* q8 = q0 + 8*HID;
        const float* cr0 = g_cos + (size_t)(qr0 + g)*32;
        const float* sr0 = g_sin + (size_t)(qr0 + g)*32;
        const float* cr8 = cr0 + 8*32;
        const float* sr8 = sr0 + 8*32;
        float x0[8], x0p[8], x8[8], x8p[8];
        #pragma unroll
        for (int ks=0; ks<8; ks++) {
            x0[ks]  = q0[8*ks + tig];
            x0p[ks] = q0[8*ks + tig + 4];
            x8[ks]  = q8[8*ks + tig];
            x8p[ks] = q8[8*ks + tig + 4];
        }
        #pragma unroll
        for (int ks=0; ks<4; ks++) {
            int i1 = 8*ks + tig, i2 = i1 + 4;
            float c0a=cr0[i1], s0a=sr0[i1], c0b=cr0[i2], s0b=sr0[i2];
            float c8a=cr8[i1], s8a=sr8[i1], c8b=cr8[i2], s8b=sr8[i2];
            qf[ks  ][0] = f2tf32(0.125f*(x0[ks]  *c0a - x0[ks+4] *s0a));
            qf[ks+4][0] = f2tf32(0.125f*(x0[ks+4]*c0a + x0[ks]   *s0a));
            qf[ks  ][2] = f2tf32(0.125f*(x0p[ks] *c0b - x0p[ks+4]*s0b));
            qf[ks+4][2] = f2tf32(0.125f*(x0p[ks+4]*c0b + x0p[ks] *s0b));
            qf[ks  ][1] = f2tf32(0.125f*(x8[ks]  *c8a - x8[ks+4] *s8a));
            qf[ks+4][1] = f2tf32(0.125f*(x8[ks+4]*c8a + x8[ks]   *s8a));
            qf[ks  ][3] = f2tf32(0.125f*(x8p[ks] *c8b - x8p[ks+4]*s8b));
            qf[ks+4][3] = f2tf32(0.125f*(x8p[ks+4]*c8b + x8p[ks] *s8b));
        }
    }

    float o[8][4];
    #pragma unroll
    for (int j=0;j<8;j++)
        #pragma unroll
        for (int t=0;t<4;t++) o[j][t] = 0.f;
    float m0 = -1e30f, m1 = -1e30f, l0 = 0.f, l1 = 0.f;

    uint32_t* Pw = Ps + warp*16*PADW;
    const int kend = (qb + 1) * 128;

    for (int kt0 = 0; kt0 < kend; kt0 += KT) {
        __syncthreads();
        // ---- stage K with fused RoPE: Ks[kt][d] ----
        {
            int kt = tid >> 2, j = tid & 3;
            int row = kt0 + kt;
            const float* kp = g_k + (size_t)row*KVDIM + kvh*HD;
            int d1 = 8*j;
            float4 xa  = *(const float4*)(kp + d1);
            float4 xa2 = *(const float4*)(kp + d1 + 4);
            float4 xb  = *(const float4*)(kp + d1 + 32);
            float4 xb2 = *(const float4*)(kp + d1 + 36);
            const float* cp = g_cos + (size_t)row*32 + d1;
            const float* sp = g_sin + (size_t)row*32 + d1;
            float4 c  = *(const float4*)cp;
            float4 c2 = *(const float4*)(cp + 4);
            float4 s  = *(const float4*)sp;
            float4 s2 = *(const float4*)(sp + 4);
            uint32_t* dst = Ks + kt*PADW + d1;
            *(uint4*)(dst)      = make_uint4(f2tf32(xa.x*c.x  - xb.x*s.x),
                                             f2tf32(xa.y*c.y  - xb.y*s.y),
                                             f2tf32(xa.z*c.z  - xb.z*s.z),
                                             f2tf32(xa.w*c.w  - xb.w*s.w));
            *(uint4*)(dst + 4)  = make_uint4(f2tf32(xa2.x*c2.x - xb2.x*s2.x),
                                             f2tf32(xa2.y*c2.y - xb2.y*s2.y),
                                             f2tf32(xa2.z*c2.z - xb2.z*s2.z),
                                             f2tf32(xa2.w*c2.w - xb2.w*s2.w));
            *(uint4*)(dst + 32) = make_uint4(f2tf32(xb.x*c.x  + xa.x*s.x),
                                             f2tf32(xb.y*c.y  + xa.y*s.y),
                                             f2tf32(xb.z*c.z  + xa.z*s.z),
                                             f2tf32(xb.w*c.w  + xa.w*s.w));
            *(uint4*)(dst + 36) = make_uint4(f2tf32(xb2.x*c2.x + xa2.x*s2.x),
                                             f2tf32(xb2.y*c2.y + xa2.y*s2.y),
                                             f2tf32(xb2.z*c2.z + xa2.z*s2.z),
                                             f2tf32(xb2.w*c2.w + xa2.w*s2.w));
        }
        // ---- stage V transposed (already tf32-rounded): raw copy ----
        {
            int kt = tid & 63;
            #pragma unroll
            for (int p=0; p<4; p++) {
                int d0 = (tid >> 6)*4 + p*16;
                uint4 f = *(const uint4*)(g_v + (size_t)(kt0 + kt)*KVDIM + kvh*HD + d0);
                Vs[(d0+0)*PADW + kt] = f.x;
                Vs[(d0+1)*PADW + kt] = f.y;
                Vs[(d0+2)*PADW + kt] = f.z;
                Vs[(d0+3)*PADW + kt] = f.w;
            }
        }
        __syncthreads();

        if (kt0 <= qr0 + 15) {
            // ---- S = Q K^T ----
            float s[8][4];
            #pragma unroll
            for (int j=0;j<8;j++)
                #pragma unroll
                for (int t=0;t<4;t++) s[j][t] = 0.f;
            #pragma unroll
            for (int ks=0; ks<8; ks++) {
                #pragma unroll
                for (int jn=0; jn<8; jn++) {
                    const uint32_t* br = Ks + (8*jn + g)*PADW + 8*ks + tig;
                    mma_tf32(s[jn], qf[ks], br[0], br[4]);
                }
            }
            // ---- causal mask (diagonal tiles only) ----
            if (kt0 + KT - 1 > qr0) {
                int r0 = qr0 + g, r1 = r0 + 8;
                #pragma unroll
                for (int jn=0; jn<8; jn++) {
                    int col = kt0 + 8*jn + 2*tig;
                    if (col     > r0) s[jn][0] = -1e30f;
                    if (col + 1 > r0) s[jn][1] = -1e30f;
                    if (col     > r1) s[jn][2] = -1e30f;
                    if (col + 1 > r1) s[jn][3] = -1e30f;
                }
            }
            // ---- online softmax ----
            float t0 = -1e30f, t1 = -1e30f;
            #pragma unroll
            for (int jn=0; jn<8; jn++) {
                t0 = fmaxf(t0, fmaxf(s[jn][0], s[jn][1]));
                t1 = fmaxf(t1, fmaxf(s[jn][2], s[jn][3]));
            }
            t0 = fmaxf(t0, __shfl_xor_sync(0xffffffffu, t0, 1));
            t0 = fmaxf(t0, __shfl_xor_sync(0xffffffffu, t0, 2));
            t1 = fmaxf(t1, __shfl_xor_sync(0xffffffffu, t1, 1));
            t1 = fmaxf(t1, __shfl_xor_sync(0xffffffffu, t1, 2));
            float mn0 = fmaxf(m0, t0), mn1 = fmaxf(m1, t1);
            float c0 = __expf(m0 - mn0), c1 = __expf(m1 - mn1);
            float ps0 = 0.f, ps1 = 0.f;
            #pragma unroll
            for (int jn=0; jn<8; jn++) {
                s[jn][0] = __expf(s[jn][0] - mn0);
                s[jn][1] = __expf(s[jn][1] - mn0);
                s[jn][2] = __expf(s[jn][2] - mn1);
                s[jn][3] = __expf(s[jn][3] - mn1);
                ps0 += s[jn][0] + s[jn][1];
                ps1 += s[jn][2] + s[jn][3];
            }
            l0 = l0*c0 + ps0;  l1 = l1*c1 + ps1;
            m0 = mn0;  m1 = mn1;
            #pragma unroll
            for (int jn=0; jn<8; jn++) {
                o[jn][0] *= c0; o[jn][1] *= c0;
                o[jn][2] *= c1; o[jn][3] *= c1;
            }
            // ---- store P (warp-private, tf32) ----
            #pragma unroll
            for (int jn=0; jn<8; jn++) {
                *(uint2*)(Pw + g*PADW     + 8*jn + 2*tig) = make_uint2(f2tf32(s[jn][0]), f2tf32(s[jn][1]));
                *(uint2*)(Pw + (g+8)*PADW + 8*jn + 2*tig) = make_uint2(f2tf32(s[jn][2]), f2tf32(s[jn][3]));
            }
            __syncwarp();
            // ---- O += P V ----
            #pragma unroll
            for (int ks=0; ks<8; ks++) {
                uint32_t a[4];
                const uint32_t* pr0 = Pw + g*PADW     + 8*ks + tig;
                const uint32_t* pr8 = Pw + (g+8)*PADW + 8*ks + tig;
                a[0] = pr0[0]; a[1] = pr8[0]; a[2] = pr0[4]; a[3] = pr8[4];
                #pragma unroll
                for (int jn=0; jn<8; jn++) {
                    const uint32_t* vr = Vs + (8*jn + g)*PADW + 8*ks + tig;
                    mma_tf32(o[jn], a, vr[0], vr[4]);
                }
            }
        }
    }

    // ---- finalize: write tf32-rounded attn (feeds wo_gemm directly) ----
    l0 += __shfl_xor_sync(0xffffffffu, l0, 1);
    l0 += __shfl_xor_sync(0xffffffffu, l0, 2);
    l1 += __shfl_xor_sync(0xffffffffu, l1, 1);
    l1 += __shfl_xor_sync(0xffffffffu, l1, 2);
    float inv0 = 1.f/l0, inv1 = 1.f/l1;
    float* o0 = g_attn + (size_t)(qr0 + g)*HID + h*HD;
    float* o8 = o0 + 8*HID;
    #pragma unroll
    for (int jn=0; jn<8; jn++) {
        *(float2*)(o0 + 8*jn + 2*tig) = make_float2(rnd_tf32(o[jn][0]*inv0), rnd_tf32(o[jn][1]*inv0));
        *(float2*)(o8 + 8*jn + 2*tig) = make_float2(rnd_tf32(o[jn][2]*inv1), rnd_tf32(o[jn][3]*inv1));
    }
}

extern "C" void kernel_launch(void* const* d_in, const int* in_sizes, int n_in,
                              void* d_out, int out_size)
{
    const float* X  = (const float*)d_in[0];
    const float* Wq = (const float*)d_in[1];
    const float* Wk = (const float*)d_in[2];
    const float* Wv = (const float*)d_in[3];
    const float* Wo = (const float*)d_in[4];
    float* out = (float*)d_out;

    const int SMEM_DYN = 4 * BM * SKW * 4;  // 73728 B
    cudaFuncSetAttribute(qkv_gemm, cudaFuncAttributeMaxDynamicSharedMemorySize, SMEM_DYN);
    cudaFuncSetAttribute(wo_gemm,  cudaFuncAttributeMaxDynamicSharedMemorySize, SMEM_DYN);
    const int SMEM_ATT = (2*KT*PADW + 8*16*PADW) * 4;  // 69632 B
    cudaFuncSetAttribute(flash_attn_tc, cudaFuncAttributeMaxDynamicSharedMemorySize, SMEM_ATT);

    // tf32 pre-rounding of inputs (bandwidth-bound, ~25us)
    cvt_inputs<<<2048, 256>>>((const float4*)X, (const float4*)Wq, (const float4*)Wk,
                              (const float4*)Wv, (const float4*)Wo);

    // fused QKV projection + rope table
    qkv_gemm<<<dim3(25, S_LEN/BM), 256, SMEM_DYN>>>();

    // causal GQA flash attention with fused RoPE (heavy-first)
    flash_attn_tc<<<dim3(S_LEN/128, NH), 256, SMEM_ATT>>>();

    // output projection
    wo_gemm<<<dim3(HID/BN, S_LEN/BM), 256, SMEM_DYN>>>(out);
}